// round 1
// baseline (speedup 1.0000x reference)
#include <cuda_runtime.h>
#include <math.h>

#define Bsz   2
#define Tsz   2048
#define Dsz   512
#define Hn    8
#define HDm   64
#define Kw    16
#define NDEPTH 3
#define ROWS  (Bsz*Tsz)   // 4096

// ---------------- scratch (static device globals; no allocation) ----------------
__device__ float g_h[ROWS * Dsz];          // LN output        (8 MB)
__device__ float g_qkv[ROWS * 3 * Dsz];    // qkv activations  (24 MB)
__device__ float g_o[ROWS * Dsz];          // attention output (8 MB)
__device__ float g_mlp[ROWS * 4 * Dsz];    // MLP hidden       (32 MB)

// ---------------- LayerNorm: one block per row (512 elems, 256 threads) ----------
__global__ void ln_kernel(const float* __restrict__ x,
                          const float* __restrict__ s,
                          const float* __restrict__ b,
                          float* __restrict__ out) {
    int row = blockIdx.x;
    int t = threadIdx.x;
    const float* xr = x + (size_t)row * Dsz;
    float v0 = xr[t], v1 = xr[t + 256];

    __shared__ float s1[256], s2[256];
    s1[t] = v0 + v1;
    s2[t] = v0 * v0 + v1 * v1;
    __syncthreads();
    #pragma unroll
    for (int o = 128; o; o >>= 1) {
        if (t < o) { s1[t] += s1[t + o]; s2[t] += s2[t + o]; }
        __syncthreads();
    }
    float mean = s1[0] * (1.0f / Dsz);
    float var  = s2[0] * (1.0f / Dsz) - mean * mean;
    float inv  = rsqrtf(var + 1e-5f);

    float* orow = out + (size_t)row * Dsz;
    orow[t]       = (v0 - mean) * inv * s[t]       + b[t];
    orow[t + 256] = (v1 - mean) * inv * s[t + 256] + b[t + 256];
}

// ---------------- Dilated sparse attention: one warp per (b, h, t) ---------------
// qkv row layout per token: [3][H][64]  (q @ 0, k @ 512, v @ 1024, head h @ h*64)
__global__ void attn_kernel(const float* __restrict__ qkv,
                            float* __restrict__ o, int dil) {
    int gw   = (blockIdx.x * blockDim.x + threadIdx.x) >> 5;
    int lane = threadIdx.x & 31;
    int t  = gw & (Tsz - 1);
    int bh = gw >> 11;          // Tsz = 2048 = 2^11
    int h  = bh & (Hn - 1);
    int b  = bh >> 3;

    const float* qp = qkv + ((size_t)(b * Tsz + t)) * (3 * Dsz) + h * HDm;
    float q0 = qp[lane], q1 = qp[lane + 32];

    int nv = t / dil + 1;
    if (nv > Kw) nv = Kw;

    float sc[Kw];
    #pragma unroll
    for (int s = 0; s < Kw; s++) {
        float e = -1e30f;
        if (s < nv) {
            int j = t - s * dil;
            const float* kp = qkv + ((size_t)(b * Tsz + j)) * (3 * Dsz) + Dsz + h * HDm;
            float p = q0 * kp[lane] + q1 * kp[lane + 32];
            #pragma unroll
            for (int m = 16; m; m >>= 1) p += __shfl_xor_sync(0xffffffffu, p, m);
            e = p * 0.125f;   // hd^-0.5 = 1/8
        }
        sc[s] = e;
    }
    float mx = sc[0];
    #pragma unroll
    for (int s = 1; s < Kw; s++) mx = fmaxf(mx, sc[s]);

    float denom = 0.f, o0 = 0.f, o1 = 0.f;
    #pragma unroll
    for (int s = 0; s < Kw; s++) {
        if (s < nv) {
            float w = expf(sc[s] - mx);
            denom += w;
            int j = t - s * dil;
            const float* vp = qkv + ((size_t)(b * Tsz + j)) * (3 * Dsz) + 2 * Dsz + h * HDm;
            o0 += w * vp[lane];
            o1 += w * vp[lane + 32];
        }
    }
    float r = 1.0f / denom;
    float* op = o + ((size_t)(b * Tsz + t)) * Dsz + h * HDm;
    op[lane]      = o0 * r;
    op[lane + 32] = o1 * r;
}

// ---------------- SGEMM 128x128x8, 256 threads, 8x8 microtile --------------------
// EPI: 0 = plain store, 1 = +bias then exact GELU, 2 = +bias then +residual
template <int EPI>
__global__ void __launch_bounds__(256)
sgemm_kernel(const float* __restrict__ A, const float* __restrict__ B,
             const float* __restrict__ bias, const float* __restrict__ res,
             float* __restrict__ C, int N, int Kdim) {
    __shared__ float As[8][128];
    __shared__ float Bs[8][128];

    int t  = threadIdx.x;
    int bx = blockIdx.x * 128;
    int by = blockIdx.y * 128;

    int aRow = t >> 1;           // 0..127
    int aCol = (t & 1) * 4;      // 0 or 4
    int bRow = t >> 5;           // 0..7
    int bCol = (t & 31) * 4;     // 0..124

    const float* Ap = A + (size_t)(by + aRow) * Kdim + aCol;
    const float* Bp = B + (size_t)bRow * N + bx + bCol;

    float acc[8][8];
    #pragma unroll
    for (int i = 0; i < 8; i++)
        #pragma unroll
        for (int j = 0; j < 8; j++) acc[i][j] = 0.f;

    int tx = t & 15, ty = t >> 4;

    for (int k0 = 0; k0 < Kdim; k0 += 8) {
        float4 av = *(const float4*)Ap;
        As[aCol + 0][aRow] = av.x;
        As[aCol + 1][aRow] = av.y;
        As[aCol + 2][aRow] = av.z;
        As[aCol + 3][aRow] = av.w;
        *(float4*)(&Bs[bRow][bCol]) = *(const float4*)Bp;
        __syncthreads();

        #pragma unroll
        for (int kk = 0; kk < 8; kk++) {
            float a[8], bb[8];
            #pragma unroll
            for (int i = 0; i < 4; i++) {
                a[i]      = As[kk][ty * 4 + i];
                a[i + 4]  = As[kk][64 + ty * 4 + i];
                bb[i]     = Bs[kk][tx * 4 + i];
                bb[i + 4] = Bs[kk][64 + tx * 4 + i];
            }
            #pragma unroll
            for (int i = 0; i < 8; i++)
                #pragma unroll
                for (int j = 0; j < 8; j++)
                    acc[i][j] = fmaf(a[i], bb[j], acc[i][j]);
        }
        __syncthreads();
        Ap += 8;
        Bp += (size_t)8 * N;
    }

    #pragma unroll
    for (int i = 0; i < 8; i++) {
        int rm = by + ((i < 4) ? (ty * 4 + i) : (64 + ty * 4 + i - 4));
        #pragma unroll
        for (int j = 0; j < 8; j++) {
            int cn = bx + ((j < 4) ? (tx * 4 + j) : (64 + tx * 4 + j - 4));
            float v = acc[i][j];
            if (EPI != 0) v += bias[cn];
            if (EPI == 1) v = 0.5f * v * (1.0f + erff(v * 0.70710678118654752f));
            if (EPI == 2) v += res[(size_t)rm * N + cn];
            C[(size_t)rm * N + cn] = v;
        }
    }
}

// ---------------- launcher -------------------------------------------------------
extern "C" void kernel_launch(void* const* d_in, const int* in_sizes, int n_in,
                              void* d_out, int out_size) {
    const float* x_in   = (const float*)d_in[0];
    const float* ln1_s  = (const float*)d_in[1];
    const float* ln1_b  = (const float*)d_in[2];
    const float* qkv_w  = (const float*)d_in[3];
    const float* proj_w = (const float*)d_in[4];
    const float* proj_b = (const float*)d_in[5];
    const float* ln2_s  = (const float*)d_in[6];
    const float* ln2_b  = (const float*)d_in[7];
    const float* w1     = (const float*)d_in[8];
    const float* b1     = (const float*)d_in[9];
    const float* w2     = (const float*)d_in[10];
    const float* b2     = (const float*)d_in[11];

    float* x = (float*)d_out;   // evolving residual stream

    float *h, *qkv, *o, *mlp;
    cudaGetSymbolAddress((void**)&h,   g_h);
    cudaGetSymbolAddress((void**)&qkv, g_qkv);
    cudaGetSymbolAddress((void**)&o,   g_o);
    cudaGetSymbolAddress((void**)&mlp, g_mlp);

    cudaMemcpyAsync(x, x_in, sizeof(float) * ROWS * Dsz, cudaMemcpyDeviceToDevice);

    for (int d = 0; d < NDEPTH; d++) {
        int dil = 1 << d;

        // h = LN1(x)
        ln_kernel<<<ROWS, 256>>>(x, ln1_s + d * Dsz, ln1_b + d * Dsz, h);

        // qkv = h @ qkv_w[d]   (4096 x 1536 x 512)
        sgemm_kernel<0><<<dim3((3 * Dsz) / 128, ROWS / 128), 256>>>(
            h, qkv_w + (size_t)d * Dsz * 3 * Dsz, nullptr, nullptr, qkv, 3 * Dsz, Dsz);

        // sparse dilated attention -> o (B,T,H,hd) contiguous
        attn_kernel<<<(ROWS * Hn) / 8, 256>>>(qkv, o, dil);

        // x = x + o @ proj_w[d] + proj_b[d]
        sgemm_kernel<2><<<dim3(Dsz / 128, ROWS / 128), 256>>>(
            o, proj_w + (size_t)d * Dsz * Dsz, proj_b + d * Dsz, x, x, Dsz, Dsz);

        // h = LN2(x)
        ln_kernel<<<ROWS, 256>>>(x, ln2_s + d * Dsz, ln2_b + d * Dsz, h);

        // mlp = gelu(h @ w1[d] + b1[d])   (4096 x 2048 x 512)
        sgemm_kernel<1><<<dim3((4 * Dsz) / 128, ROWS / 128), 256>>>(
            h, w1 + (size_t)d * Dsz * 4 * Dsz, b1 + (size_t)d * 4 * Dsz, nullptr,
            mlp, 4 * Dsz, Dsz);

        // x = x + mlp @ w2[d] + b2[d]     (4096 x 512 x 2048)
        sgemm_kernel<2><<<dim3(Dsz / 128, ROWS / 128), 256>>>(
            mlp, w2 + (size_t)d * 4 * Dsz * Dsz, b2 + d * Dsz, x, x, Dsz, 4 * Dsz);
    }
}

// round 3
// speedup vs baseline: 2.9140x; 2.9140x over previous
#include <cuda_runtime.h>
#include <math.h>
#include <stdint.h>

#define Bsz   2
#define Tsz   2048
#define Dsz   512
#define Hn    8
#define HDm   64
#define Kw    16
#define NDEPTH 3
#define ROWS  (Bsz*Tsz)   // 4096

// ---------------- scratch (static device globals; no allocation) ----------------
__device__ float g_h[ROWS * Dsz];
__device__ float g_qkv[ROWS * 3 * Dsz];
__device__ float g_o[ROWS * Dsz];
__device__ float g_mlp[ROWS * 4 * Dsz];
// tf32-rounded weights (same layout as originals: [K,N])
__device__ float g_qkvw_c[NDEPTH * Dsz * 3 * Dsz];
__device__ float g_projw_c[NDEPTH * Dsz * Dsz];
__device__ float g_w1_c[NDEPTH * Dsz * 4 * Dsz];
__device__ float g_w2_c[NDEPTH * 4 * Dsz * Dsz];

// ---------------- helpers ----------------------------------------------------------
__device__ __forceinline__ uint32_t smem_u32(const void* p) {
    uint32_t a;
    asm("{ .reg .u64 t; cvta.to.shared.u64 t, %1; cvt.u32.u64 %0, t; }" : "=r"(a) : "l"(p));
    return a;
}
__device__ __forceinline__ float tf32r(float f) {
    uint32_t r; asm("cvt.rna.tf32.f32 %0, %1;" : "=r"(r) : "f"(f));
    return __uint_as_float(r);
}
__device__ __forceinline__ void cp16(uint32_t s, const void* g) {
    asm volatile("cp.async.cg.shared.global [%0], [%1], 16;" :: "r"(s), "l"(g));
}
__device__ __forceinline__ void mma_tf32(float* c, const uint32_t* a, const uint32_t* b) {
    asm volatile(
        "mma.sync.aligned.m16n8k8.row.col.f32.tf32.tf32.f32 "
        "{%0,%1,%2,%3}, {%4,%5,%6,%7}, {%8,%9}, {%0,%1,%2,%3};"
        : "+f"(c[0]), "+f"(c[1]), "+f"(c[2]), "+f"(c[3])
        : "r"(a[0]), "r"(a[1]), "r"(a[2]), "r"(a[3]), "r"(b[0]), "r"(b[1]));
}

// ---------------- tf32 rounding copy (weights) --------------------------------------
__global__ void cvt_kernel(const float4* __restrict__ in, float4* __restrict__ out, int n4) {
    int i = blockIdx.x * blockDim.x + threadIdx.x;
    if (i < n4) {
        float4 v = in[i];
        v.x = tf32r(v.x); v.y = tf32r(v.y); v.z = tf32r(v.z); v.w = tf32r(v.w);
        out[i] = v;
    }
}

// ---------------- LayerNorm (stores tf32-rounded output) ----------------------------
__global__ void ln_kernel(const float* __restrict__ x, const float* __restrict__ s,
                          const float* __restrict__ b, float* __restrict__ out) {
    int row = blockIdx.x;
    int t = threadIdx.x;
    const float* xr = x + (size_t)row * Dsz;
    float v0 = xr[t], v1 = xr[t + 256];
    __shared__ float s1[256], s2[256];
    s1[t] = v0 + v1;
    s2[t] = v0 * v0 + v1 * v1;
    __syncthreads();
    #pragma unroll
    for (int o = 128; o; o >>= 1) {
        if (t < o) { s1[t] += s1[t + o]; s2[t] += s2[t + o]; }
        __syncthreads();
    }
    float mean = s1[0] * (1.0f / Dsz);
    float var  = s2[0] * (1.0f / Dsz) - mean * mean;
    float inv  = rsqrtf(var + 1e-5f);
    float* orow = out + (size_t)row * Dsz;
    orow[t]       = tf32r((v0 - mean) * inv * s[t]       + b[t]);
    orow[t + 256] = tf32r((v1 - mean) * inv * s[t + 256] + b[t + 256]);
}

// ---------------- Dilated sparse attention (stores tf32-rounded output) -------------
__global__ void attn_kernel(const float* __restrict__ qkv, float* __restrict__ o, int dil) {
    int gw   = (blockIdx.x * blockDim.x + threadIdx.x) >> 5;
    int lane = threadIdx.x & 31;
    int t  = gw & (Tsz - 1);
    int bh = gw >> 11;
    int h  = bh & (Hn - 1);
    int b  = bh >> 3;

    const float* qp = qkv + ((size_t)(b * Tsz + t)) * (3 * Dsz) + h * HDm;
    float q0 = qp[lane], q1 = qp[lane + 32];
    int nv = t / dil + 1;
    if (nv > Kw) nv = Kw;

    float sc[Kw];
    #pragma unroll
    for (int s = 0; s < Kw; s++) {
        float e = -1e30f;
        if (s < nv) {
            int j = t - s * dil;
            const float* kp = qkv + ((size_t)(b * Tsz + j)) * (3 * Dsz) + Dsz + h * HDm;
            float p = q0 * kp[lane] + q1 * kp[lane + 32];
            #pragma unroll
            for (int m = 16; m; m >>= 1) p += __shfl_xor_sync(0xffffffffu, p, m);
            e = p * 0.125f;
        }
        sc[s] = e;
    }
    float mx = sc[0];
    #pragma unroll
    for (int s = 1; s < Kw; s++) mx = fmaxf(mx, sc[s]);

    float denom = 0.f, o0 = 0.f, o1 = 0.f;
    #pragma unroll
    for (int s = 0; s < Kw; s++) {
        if (s < nv) {
            float w = expf(sc[s] - mx);
            denom += w;
            int j = t - s * dil;
            const float* vp = qkv + ((size_t)(b * Tsz + j)) * (3 * Dsz) + 2 * Dsz + h * HDm;
            o0 += w * vp[lane];
            o1 += w * vp[lane + 32];
        }
    }
    float r = 1.0f / denom;
    float* op = o + ((size_t)(b * Tsz + t)) * Dsz + h * HDm;
    op[lane]      = tf32r(o0 * r);
    op[lane + 32] = tf32r(o1 * r);
}

// ---------------- tf32 mma.sync GEMM: C[M,N] = A[M,K] @ B[K,N] ----------------------
// 128 x BN_ x 32 tile, 256 threads (8 warps: 4M x 2N), warp tile 32 x BN_/2.
// A smem [m][k] stride 36; B smem [k][n] stride BN_+8. Double-buffered cp.async.
// EPI: 0 = plain, 1 = +bias + exact GELU (store tf32-rounded), 2 = +bias + residual
template <int BN_, int EPI>
__global__ void __launch_bounds__(256)
mma_gemm(const float* __restrict__ A, const float* __restrict__ B,
         const float* __restrict__ bias, const float* __restrict__ res,
         float* __restrict__ C, int N, int K) {
    constexpr int BM = 128, BK = 32;
    constexpr int AST = BK + 4;          // 36 floats
    constexpr int BST = BN_ + 8;         // %32 == 8 -> conflict-free frag loads
    constexpr int ABYTES = BM * AST * 4; // 18432
    constexpr int BBYTES = BK * BST * 4;
    constexpr int WN = BN_ / 2;          // warp N extent
    constexpr int NT = WN / 8;           // n-tiles per warp
    constexpr int BSEGS = BN_ / 4;       // 16B segs per B row
    constexpr int BRPP  = 256 / BSEGS;   // B rows per pass
    constexpr int BPASS = BK / BRPP;

    extern __shared__ char dsm[];
    const uint32_t sbase = smem_u32(dsm);

    const int tid  = threadIdx.x;
    const int w    = tid >> 5, lane = tid & 31;
    const int wm   = w & 3,   wn   = w >> 2;
    const int g    = lane >> 2, t4 = lane & 3;
    const int bx   = blockIdx.x * BN_, by = blockIdx.y * BM;

    const int arow = tid >> 3, aseg = tid & 7;
    const int brow = tid / BSEGS, bseg = tid % BSEGS;

    const float* Ag = A + (size_t)(by + arow) * K + aseg * 4;
    const float* Bg = B + (size_t)brow * N + bx + bseg * 4;
    const uint32_t As0 = sbase + (arow * AST + aseg * 4) * 4;
    const uint32_t Bs0 = sbase + 2 * ABYTES + (brow * BST + bseg * 4) * 4;

    float acc[2][NT][4];
    #pragma unroll
    for (int i = 0; i < 2; i++)
        #pragma unroll
        for (int j = 0; j < NT; j++)
            #pragma unroll
            for (int q = 0; q < 4; q++) acc[i][j][q] = 0.f;

    const int nch = K / BK;

    // prologue: chunk 0 -> buffer 0
    #pragma unroll
    for (int p = 0; p < 4; p++)
        cp16(As0 + p * 32 * AST * 4, Ag + (size_t)p * 32 * K);
    #pragma unroll
    for (int p = 0; p < BPASS; p++)
        cp16(Bs0 + p * BRPP * BST * 4, Bg + (size_t)p * BRPP * N);
    asm volatile("cp.async.commit_group;");

    for (int c = 0; c < nch; ++c) {
        const int buf = c & 1;
        if (c + 1 < nch) {
            const int nb = buf ^ 1;
            const float* Agn = Ag + (c + 1) * BK;
            const float* Bgn = Bg + (size_t)(c + 1) * BK * N;
            #pragma unroll
            for (int p = 0; p < 4; p++)
                cp16(As0 + nb * ABYTES + p * 32 * AST * 4, Agn + (size_t)p * 32 * K);
            #pragma unroll
            for (int p = 0; p < BPASS; p++)
                cp16(Bs0 + 2 * (nb - buf) * 0 + nb * BBYTES + p * BRPP * BST * 4, Bgn + (size_t)p * BRPP * N);
            asm volatile("cp.async.commit_group;");
            asm volatile("cp.async.wait_group 1;");
        } else {
            asm volatile("cp.async.wait_group 0;");
        }
        __syncthreads();

        const float* as = (const float*)(dsm + buf * ABYTES);
        const float* bs = (const float*)(dsm + 2 * ABYTES + buf * BBYTES);

        #pragma unroll
        for (int ks = 0; ks < 4; ks++) {
            const int k0 = ks * 8;
            uint32_t af[2][4], bf[NT][2];
            #pragma unroll
            for (int mt = 0; mt < 2; mt++) {
                const int rb = wm * 32 + mt * 16;
                af[mt][0] = __float_as_uint(as[(rb + g)     * AST + k0 + t4]);
                af[mt][1] = __float_as_uint(as[(rb + g + 8) * AST + k0 + t4]);
                af[mt][2] = __float_as_uint(as[(rb + g)     * AST + k0 + t4 + 4]);
                af[mt][3] = __float_as_uint(as[(rb + g + 8) * AST + k0 + t4 + 4]);
            }
            #pragma unroll
            for (int nt = 0; nt < NT; nt++) {
                const int col = wn * WN + nt * 8 + g;
                bf[nt][0] = __float_as_uint(bs[(k0 + t4)     * BST + col]);
                bf[nt][1] = __float_as_uint(bs[(k0 + t4 + 4) * BST + col]);
            }
            #pragma unroll
            for (int mt = 0; mt < 2; mt++)
                #pragma unroll
                for (int nt = 0; nt < NT; nt++)
                    mma_tf32(acc[mt][nt], af[mt], bf[nt]);
        }
        __syncthreads();
    }

    // epilogue: registers -> global with fused ops
    #pragma unroll
    for (int mt = 0; mt < 2; mt++) {
        const int r0 = by + wm * 32 + mt * 16 + g;
        #pragma unroll
        for (int nt = 0; nt < NT; nt++) {
            const int col = bx + wn * WN + nt * 8 + 2 * t4;
            float v0 = acc[mt][nt][0], v1 = acc[mt][nt][1];
            float v2 = acc[mt][nt][2], v3 = acc[mt][nt][3];
            if (EPI != 0) {
                float2 bb = *(const float2*)&bias[col];
                v0 += bb.x; v1 += bb.y; v2 += bb.x; v3 += bb.y;
            }
            if (EPI == 1) {
                v0 = tf32r(0.5f * v0 * (1.0f + erff(v0 * 0.70710678118654752f)));
                v1 = tf32r(0.5f * v1 * (1.0f + erff(v1 * 0.70710678118654752f)));
                v2 = tf32r(0.5f * v2 * (1.0f + erff(v2 * 0.70710678118654752f)));
                v3 = tf32r(0.5f * v3 * (1.0f + erff(v3 * 0.70710678118654752f)));
            }
            if (EPI == 2) {
                float2 ra = *(const float2*)&res[(size_t)r0 * N + col];
                float2 rb = *(const float2*)&res[(size_t)(r0 + 8) * N + col];
                v0 += ra.x; v1 += ra.y; v2 += rb.x; v3 += rb.y;
            }
            float2 o01 = { v0, v1 }, o23 = { v2, v3 };
            *(float2*)&C[(size_t)r0 * N + col]       = o01;
            *(float2*)&C[(size_t)(r0 + 8) * N + col] = o23;
        }
    }
}

// ---------------- launcher -----------------------------------------------------------
#define SMEM128 (2*128*36*4 + 2*32*136*4)   // 71680
#define SMEM64  (2*128*36*4 + 2*32*72*4)    // 55296

extern "C" void kernel_launch(void* const* d_in, const int* in_sizes, int n_in,
                              void* d_out, int out_size) {
    const float* x_in   = (const float*)d_in[0];
    const float* ln1_s  = (const float*)d_in[1];
    const float* ln1_b  = (const float*)d_in[2];
    const float* qkv_w  = (const float*)d_in[3];
    const float* proj_w = (const float*)d_in[4];
    const float* proj_b = (const float*)d_in[5];
    const float* ln2_s  = (const float*)d_in[6];
    const float* ln2_b  = (const float*)d_in[7];
    const float* w1     = (const float*)d_in[8];
    const float* b1     = (const float*)d_in[9];
    const float* w2     = (const float*)d_in[10];
    const float* b2     = (const float*)d_in[11];

    float* x = (float*)d_out;

    float *h, *qkv, *o, *mlp, *qkvc, *projc, *w1c, *w2c;
    cudaGetSymbolAddress((void**)&h,     g_h);
    cudaGetSymbolAddress((void**)&qkv,   g_qkv);
    cudaGetSymbolAddress((void**)&o,     g_o);
    cudaGetSymbolAddress((void**)&mlp,   g_mlp);
    cudaGetSymbolAddress((void**)&qkvc,  g_qkvw_c);
    cudaGetSymbolAddress((void**)&projc, g_projw_c);
    cudaGetSymbolAddress((void**)&w1c,   g_w1_c);
    cudaGetSymbolAddress((void**)&w2c,   g_w2_c);

    cudaFuncSetAttribute(mma_gemm<128,0>, cudaFuncAttributeMaxDynamicSharedMemorySize, SMEM128);
    cudaFuncSetAttribute(mma_gemm<128,1>, cudaFuncAttributeMaxDynamicSharedMemorySize, SMEM128);
    cudaFuncSetAttribute(mma_gemm<64,2>,  cudaFuncAttributeMaxDynamicSharedMemorySize, SMEM64);

    cudaMemcpyAsync(x, x_in, sizeof(float) * ROWS * Dsz, cudaMemcpyDeviceToDevice);

    // tf32-round all weights once (RNA), same layout
    {
        int n4;
        n4 = NDEPTH * Dsz * 3 * Dsz / 4;
        cvt_kernel<<<(n4 + 255) / 256, 256>>>((const float4*)qkv_w, (float4*)qkvc, n4);
        n4 = NDEPTH * Dsz * Dsz / 4;
        cvt_kernel<<<(n4 + 255) / 256, 256>>>((const float4*)proj_w, (float4*)projc, n4);
        n4 = NDEPTH * Dsz * 4 * Dsz / 4;
        cvt_kernel<<<(n4 + 255) / 256, 256>>>((const float4*)w1, (float4*)w1c, n4);
        n4 = NDEPTH * 4 * Dsz * Dsz / 4;
        cvt_kernel<<<(n4 + 255) / 256, 256>>>((const float4*)w2, (float4*)w2c, n4);
    }

    for (int d = 0; d < NDEPTH; d++) {
        int dil = 1 << d;

        ln_kernel<<<ROWS, 256>>>(x, ln1_s + d * Dsz, ln1_b + d * Dsz, h);

        // qkv = h @ qkv_w   (4096 x 1536 x 512)
        mma_gemm<128,0><<<dim3((3 * Dsz) / 128, ROWS / 128), 256, SMEM128>>>(
            h, qkvc + (size_t)d * Dsz * 3 * Dsz, nullptr, nullptr, qkv, 3 * Dsz, Dsz);

        attn_kernel<<<(ROWS * Hn) / 8, 256>>>(qkv, o, dil);

        // x = x + o @ proj_w + proj_b   (4096 x 512 x 512)
        mma_gemm<64,2><<<dim3(Dsz / 64, ROWS / 128), 256, SMEM64>>>(
            o, projc + (size_t)d * Dsz * Dsz, proj_b + d * Dsz, x, x, Dsz, Dsz);

        ln_kernel<<<ROWS, 256>>>(x, ln2_s + d * Dsz, ln2_b + d * Dsz, h);

        // mlp = gelu(h @ w1 + b1)   (4096 x 2048 x 512)
        mma_gemm<128,1><<<dim3((4 * Dsz) / 128, ROWS / 128), 256, SMEM128>>>(
            h, w1c + (size_t)d * Dsz * 4 * Dsz, b1 + (size_t)d * 4 * Dsz, nullptr,
            mlp, 4 * Dsz, Dsz);

        // x = x + mlp @ w2 + b2   (4096 x 512 x 2048)
        mma_gemm<64,2><<<dim3(Dsz / 64, ROWS / 128), 256, SMEM64>>>(
            mlp, w2c + (size_t)d * 4 * Dsz * Dsz, b2 + d * Dsz, x, x, Dsz, 4 * Dsz);
    }
}

// round 4
// speedup vs baseline: 3.6344x; 1.2473x over previous
#include <cuda_runtime.h>
#include <cuda_fp16.h>
#include <math.h>
#include <stdint.h>

#define Bsz   2
#define Tsz   2048
#define Dsz   512
#define Hn    8
#define HDm   64
#define Kw    16
#define NDEPTH 3
#define ROWS  (Bsz*Tsz)   // 4096

// ---------------- scratch (static device globals; no allocation) ----------------
__device__ __half g_h[ROWS * Dsz];
__device__ __half g_qkv[ROWS * 3 * Dsz];
__device__ __half g_o[ROWS * Dsz];
__device__ __half g_mlp[ROWS * 4 * Dsz];
// transposed fp16 weights ([N,K], K contiguous)
__device__ __half g_qkvwT[NDEPTH * 3 * Dsz * Dsz];
__device__ __half g_projwT[NDEPTH * Dsz * Dsz];
__device__ __half g_w1T[NDEPTH * 4 * Dsz * Dsz];
__device__ __half g_w2T[NDEPTH * Dsz * 4 * Dsz];

// ---------------- helpers ----------------------------------------------------------
__device__ __forceinline__ uint32_t smem_u32(const void* p) {
    uint32_t a;
    asm("{ .reg .u64 t; cvta.to.shared.u64 t, %1; cvt.u32.u64 %0, t; }" : "=r"(a) : "l"(p));
    return a;
}
__device__ __forceinline__ void cp16(uint32_t s, const void* g) {
    asm volatile("cp.async.cg.shared.global [%0], [%1], 16;" :: "r"(s), "l"(g));
}
__device__ __forceinline__ void ldsm4(uint32_t* r, uint32_t addr) {
    asm volatile("ldmatrix.sync.aligned.m8n8.x4.shared.b16 {%0,%1,%2,%3}, [%4];"
                 : "=r"(r[0]), "=r"(r[1]), "=r"(r[2]), "=r"(r[3]) : "r"(addr));
}
__device__ __forceinline__ void mma_f16(float* c, const uint32_t* a, const uint32_t* b) {
    asm volatile(
        "mma.sync.aligned.m16n8k16.row.col.f32.f16.f16.f32 "
        "{%0,%1,%2,%3}, {%4,%5,%6,%7}, {%8,%9}, {%0,%1,%2,%3};"
        : "+f"(c[0]), "+f"(c[1]), "+f"(c[2]), "+f"(c[3])
        : "r"(a[0]), "r"(a[1]), "r"(a[2]), "r"(a[3]), "r"(b[0]), "r"(b[1]));
}

// ---------------- weight transpose+convert: fp32 [R][C] -> fp16 [C][R] -------------
__global__ void transpose_cvt(const float* __restrict__ in, __half* __restrict__ out,
                              int R, int C) {
    __shared__ float tile[32][33];
    int c0 = blockIdx.x * 32, r0 = blockIdx.y * 32;
    int tx = threadIdx.x, ty = threadIdx.y;   // (32, 8)
    #pragma unroll
    for (int i = 0; i < 32; i += 8)
        tile[ty + i][tx] = in[(size_t)(r0 + ty + i) * C + c0 + tx];
    __syncthreads();
    #pragma unroll
    for (int i = 0; i < 32; i += 8)
        out[(size_t)(c0 + ty + i) * R + r0 + tx] = __float2half(tile[tx][ty + i]);
}

// ---------------- LayerNorm (fp32 in, fp16 out) -------------------------------------
__global__ void ln_kernel(const float* __restrict__ x, const float* __restrict__ s,
                          const float* __restrict__ b, __half* __restrict__ out) {
    int row = blockIdx.x;
    int t = threadIdx.x;
    const float* xr = x + (size_t)row * Dsz;
    float v0 = xr[t], v1 = xr[t + 256];
    __shared__ float s1[256], s2[256];
    s1[t] = v0 + v1;
    s2[t] = v0 * v0 + v1 * v1;
    __syncthreads();
    #pragma unroll
    for (int o = 128; o; o >>= 1) {
        if (t < o) { s1[t] += s1[t + o]; s2[t] += s2[t + o]; }
        __syncthreads();
    }
    float mean = s1[0] * (1.0f / Dsz);
    float var  = s2[0] * (1.0f / Dsz) - mean * mean;
    float inv  = rsqrtf(var + 1e-5f);
    __half* orow = out + (size_t)row * Dsz;
    orow[t]       = __float2half((v0 - mean) * inv * s[t]       + b[t]);
    orow[t + 256] = __float2half((v1 - mean) * inv * s[t + 256] + b[t + 256]);
}

// ---------------- Dilated sparse attention (fp16 qkv, fp16 out, fp32 math) ----------
__global__ void attn_kernel(const __half* __restrict__ qkv, __half* __restrict__ o, int dil) {
    int gw   = (blockIdx.x * blockDim.x + threadIdx.x) >> 5;
    int lane = threadIdx.x & 31;
    int t  = gw & (Tsz - 1);
    int bh = gw >> 11;
    int h  = bh & (Hn - 1);
    int b  = bh >> 3;

    const __half* qp = qkv + ((size_t)(b * Tsz + t)) * (3 * Dsz) + h * HDm;
    float q0 = __half2float(qp[lane]), q1 = __half2float(qp[lane + 32]);
    int nv = t / dil + 1;
    if (nv > Kw) nv = Kw;

    float sc[Kw];
    #pragma unroll
    for (int s = 0; s < Kw; s++) {
        float e = -1e30f;
        if (s < nv) {
            int j = t - s * dil;
            const __half* kp = qkv + ((size_t)(b * Tsz + j)) * (3 * Dsz) + Dsz + h * HDm;
            float p = q0 * __half2float(kp[lane]) + q1 * __half2float(kp[lane + 32]);
            #pragma unroll
            for (int m = 16; m; m >>= 1) p += __shfl_xor_sync(0xffffffffu, p, m);
            e = p * 0.125f;
        }
        sc[s] = e;
    }
    float mx = sc[0];
    #pragma unroll
    for (int s = 1; s < Kw; s++) mx = fmaxf(mx, sc[s]);

    float denom = 0.f, o0 = 0.f, o1 = 0.f;
    #pragma unroll
    for (int s = 0; s < Kw; s++) {
        if (s < nv) {
            float w = expf(sc[s] - mx);
            denom += w;
            int j = t - s * dil;
            const __half* vp = qkv + ((size_t)(b * Tsz + j)) * (3 * Dsz) + 2 * Dsz + h * HDm;
            o0 += w * __half2float(vp[lane]);
            o1 += w * __half2float(vp[lane + 32]);
        }
    }
    float r = 1.0f / denom;
    __half* op = o + ((size_t)(b * Tsz + t)) * Dsz + h * HDm;
    op[lane]      = __float2half(o0 * r);
    op[lane + 32] = __float2half(o1 * r);
}

// ---------------- fp16 mma.sync GEMM: C[M,N] = A[M,K] @ Bt[N,K]^T --------------------
// 128 x BN_ x 32 tile, 256 threads (8 warps: 4M x 2N). A/B smem rows padded to 40
// halves (conflict-free ldmatrix). Double-buffered cp.async.
// EPI: 0 = store half, 1 = +bias + exact GELU -> half, 2 = +bias + residual -> float
template <int BN_, int EPI>
__global__ void __launch_bounds__(256)
mma_gemm(const __half* __restrict__ A, const __half* __restrict__ Bt,
         const float* __restrict__ bias, const float* __restrict__ res,
         void* __restrict__ Cv, int N, int K) {
    constexpr int BM = 128, BK = 32;
    constexpr int RST = 40;                      // padded row stride (halves)
    constexpr int ABYTES = BM * RST * 2;         // 10240
    constexpr int BBYTES = BN_ * RST * 2;
    constexpr int WN = BN_ / 2;                  // warp N extent
    constexpr int NT = WN / 8;                   // n8 tiles per warp
    constexpr int NPAIR = NT / 2;                // ldmatrix.x4 pairs
    constexpr int BCH = BN_ * 4;                 // B cp chunks per buffer
    constexpr int BITER = BCH / 256;

    extern __shared__ char dsm[];
    const uint32_t sbase = smem_u32(dsm);
    const uint32_t bbase = sbase + 2 * ABYTES;

    const int tid  = threadIdx.x;
    const int w    = tid >> 5, lane = tid & 31;
    const int wm   = w & 3,   wn   = w >> 2;
    const int g    = lane >> 2, t4 = lane & 3;
    const int quad = lane >> 3, qr = lane & 7;
    const int bx   = blockIdx.x * BN_, by = blockIdx.y * BM;

    // cp.async source/dest (A: 2 chunks/thread; B: BITER chunks/thread)
    const __half* Ag[2]; uint32_t Asm[2];
    #pragma unroll
    for (int i = 0; i < 2; i++) {
        int e = tid + i * 256, row = e >> 2, seg = e & 3;
        Ag[i]  = A + (size_t)(by + row) * K + seg * 8;
        Asm[i] = sbase + (row * RST + seg * 8) * 2;
    }
    const __half* Bg[BITER]; uint32_t Bsm[BITER];
    #pragma unroll
    for (int i = 0; i < BITER; i++) {
        int e = tid + i * 256, row = e >> 2, seg = e & 3;
        Bg[i]  = Bt + (size_t)(bx + row) * K + seg * 8;
        Bsm[i] = bbase + (row * RST + seg * 8) * 2;
    }

    // ldmatrix lane addresses (byte offsets within a buffer, before +k0)
    uint32_t aAddr[2], bAddr[NPAIR];
    #pragma unroll
    for (int mt = 0; mt < 2; mt++) {
        int row = wm * 32 + mt * 16 + (quad & 1) * 8 + qr;
        int col = (quad >> 1) * 8;
        aAddr[mt] = sbase + (row * RST + col) * 2;
    }
    #pragma unroll
    for (int p = 0; p < NPAIR; p++) {
        int row = wn * WN + p * 16 + (quad & 1) * 8 + qr;
        int col = (quad >> 1) * 8;
        bAddr[p] = bbase + (row * RST + col) * 2;
    }

    float acc[2][NT][4];
    #pragma unroll
    for (int i = 0; i < 2; i++)
        #pragma unroll
        for (int j = 0; j < NT; j++)
            #pragma unroll
            for (int q = 0; q < 4; q++) acc[i][j][q] = 0.f;

    const int nch = K / BK;

    // prologue
    #pragma unroll
    for (int i = 0; i < 2; i++) cp16(Asm[i], Ag[i]);
    #pragma unroll
    for (int i = 0; i < BITER; i++) cp16(Bsm[i], Bg[i]);
    asm volatile("cp.async.commit_group;");

    for (int c = 0; c < nch; ++c) {
        const int buf = c & 1;
        if (c + 1 < nch) {
            const int nb = buf ^ 1;
            const int ko = (c + 1) * BK;
            #pragma unroll
            for (int i = 0; i < 2; i++) cp16(Asm[i] + nb * ABYTES, Ag[i] + ko);
            #pragma unroll
            for (int i = 0; i < BITER; i++) cp16(Bsm[i] + nb * BBYTES, Bg[i] + ko);
            asm volatile("cp.async.commit_group;");
            asm volatile("cp.async.wait_group 1;");
        } else {
            asm volatile("cp.async.wait_group 0;");
        }
        __syncthreads();

        const uint32_t aOff = buf * ABYTES;
        const uint32_t bOff = buf * BBYTES;
        #pragma unroll
        for (int ks = 0; ks < 2; ks++) {
            const uint32_t kb = ks * 32;   // 16 halves
            uint32_t af[2][4];
            #pragma unroll
            for (int mt = 0; mt < 2; mt++) ldsm4(af[mt], aAddr[mt] + aOff + kb);
            uint32_t bf[NPAIR][4];
            #pragma unroll
            for (int p = 0; p < NPAIR; p++) ldsm4(bf[p], bAddr[p] + bOff + kb);
            #pragma unroll
            for (int mt = 0; mt < 2; mt++)
                #pragma unroll
                for (int p = 0; p < NPAIR; p++) {
                    uint32_t b0[2] = { bf[p][0], bf[p][2] };
                    uint32_t b1[2] = { bf[p][1], bf[p][3] };
                    mma_f16(acc[mt][2 * p],     af[mt], b0);
                    mma_f16(acc[mt][2 * p + 1], af[mt], b1);
                }
        }
        __syncthreads();
    }

    // epilogue
    #pragma unroll
    for (int mt = 0; mt < 2; mt++) {
        const int r0 = by + wm * 32 + mt * 16 + g;
        #pragma unroll
        for (int nt = 0; nt < NT; nt++) {
            const int col = bx + wn * WN + nt * 8 + 2 * t4;
            float v0 = acc[mt][nt][0], v1 = acc[mt][nt][1];
            float v2 = acc[mt][nt][2], v3 = acc[mt][nt][3];
            if (EPI != 0) {
                float2 bb = *(const float2*)&bias[col];
                v0 += bb.x; v1 += bb.y; v2 += bb.x; v3 += bb.y;
            }
            if (EPI == 1) {
                v0 = 0.5f * v0 * (1.0f + erff(v0 * 0.70710678118654752f));
                v1 = 0.5f * v1 * (1.0f + erff(v1 * 0.70710678118654752f));
                v2 = 0.5f * v2 * (1.0f + erff(v2 * 0.70710678118654752f));
                v3 = 0.5f * v3 * (1.0f + erff(v3 * 0.70710678118654752f));
            }
            if (EPI == 2) {
                float* C = (float*)Cv;
                float2 ra = *(const float2*)&res[(size_t)r0 * N + col];
                float2 rb = *(const float2*)&res[(size_t)(r0 + 8) * N + col];
                float2 o01 = { v0 + ra.x, v1 + ra.y };
                float2 o23 = { v2 + rb.x, v3 + rb.y };
                *(float2*)&C[(size_t)r0 * N + col]       = o01;
                *(float2*)&C[(size_t)(r0 + 8) * N + col] = o23;
            } else {
                __half* C = (__half*)Cv;
                *(__half2*)&C[(size_t)r0 * N + col]       = __floats2half2_rn(v0, v1);
                *(__half2*)&C[(size_t)(r0 + 8) * N + col] = __floats2half2_rn(v2, v3);
            }
        }
    }
}

// ---------------- launcher -----------------------------------------------------------
#define SMEM128 (2*10240 + 2*10240)   // 40960
#define SMEM64  (2*10240 + 2*5120)    // 30720

extern "C" void kernel_launch(void* const* d_in, const int* in_sizes, int n_in,
                              void* d_out, int out_size) {
    const float* x_in   = (const float*)d_in[0];
    const float* ln1_s  = (const float*)d_in[1];
    const float* ln1_b  = (const float*)d_in[2];
    const float* qkv_w  = (const float*)d_in[3];
    const float* proj_w = (const float*)d_in[4];
    const float* proj_b = (const float*)d_in[5];
    const float* ln2_s  = (const float*)d_in[6];
    const float* ln2_b  = (const float*)d_in[7];
    const float* w1     = (const float*)d_in[8];
    const float* b1     = (const float*)d_in[9];
    const float* w2     = (const float*)d_in[10];
    const float* b2     = (const float*)d_in[11];

    float* x = (float*)d_out;

    __half *h, *qkv, *o, *mlp, *qkvT, *projT, *w1T, *w2T;
    cudaGetSymbolAddress((void**)&h,     g_h);
    cudaGetSymbolAddress((void**)&qkv,   g_qkv);
    cudaGetSymbolAddress((void**)&o,     g_o);
    cudaGetSymbolAddress((void**)&mlp,   g_mlp);
    cudaGetSymbolAddress((void**)&qkvT,  g_qkvwT);
    cudaGetSymbolAddress((void**)&projT, g_projwT);
    cudaGetSymbolAddress((void**)&w1T,   g_w1T);
    cudaGetSymbolAddress((void**)&w2T,   g_w2T);

    cudaFuncSetAttribute(mma_gemm<128,0>, cudaFuncAttributeMaxDynamicSharedMemorySize, SMEM128);
    cudaFuncSetAttribute(mma_gemm<128,1>, cudaFuncAttributeMaxDynamicSharedMemorySize, SMEM128);
    cudaFuncSetAttribute(mma_gemm<64,2>,  cudaFuncAttributeMaxDynamicSharedMemorySize, SMEM64);

    cudaMemcpyAsync(x, x_in, sizeof(float) * ROWS * Dsz, cudaMemcpyDeviceToDevice);

    // transpose+convert all weights: fp32 [K,N] -> fp16 [N,K]
    for (int d = 0; d < NDEPTH; d++) {
        transpose_cvt<<<dim3((3 * Dsz) / 32, Dsz / 32), dim3(32, 8)>>>(
            qkv_w + (size_t)d * Dsz * 3 * Dsz, qkvT + (size_t)d * 3 * Dsz * Dsz, Dsz, 3 * Dsz);
        transpose_cvt<<<dim3(Dsz / 32, Dsz / 32), dim3(32, 8)>>>(
            proj_w + (size_t)d * Dsz * Dsz, projT + (size_t)d * Dsz * Dsz, Dsz, Dsz);
        transpose_cvt<<<dim3((4 * Dsz) / 32, Dsz / 32), dim3(32, 8)>>>(
            w1 + (size_t)d * Dsz * 4 * Dsz, w1T + (size_t)d * 4 * Dsz * Dsz, Dsz, 4 * Dsz);
        transpose_cvt<<<dim3(Dsz / 32, (4 * Dsz) / 32), dim3(32, 8)>>>(
            w2 + (size_t)d * 4 * Dsz * Dsz, w2T + (size_t)d * Dsz * 4 * Dsz, 4 * Dsz, Dsz);
    }

    for (int d = 0; d < NDEPTH; d++) {
        int dil = 1 << d;

        ln_kernel<<<ROWS, 256>>>(x, ln1_s + d * Dsz, ln1_b + d * Dsz, h);

        // qkv = h @ qkv_w   (4096 x 1536 x 512)
        mma_gemm<128,0><<<dim3((3 * Dsz) / 128, ROWS / 128), 256, SMEM128>>>(
            h, qkvT + (size_t)d * 3 * Dsz * Dsz, nullptr, nullptr, qkv, 3 * Dsz, Dsz);

        attn_kernel<<<(ROWS * Hn) / 8, 256>>>(qkv, o, dil);

        // x = x + o @ proj_w + proj_b   (4096 x 512 x 512)
        mma_gemm<64,2><<<dim3(Dsz / 64, ROWS / 128), 256, SMEM64>>>(
            o, projT + (size_t)d * Dsz * Dsz, proj_b + d * Dsz, x, x, Dsz, Dsz);

        ln_kernel<<<ROWS, 256>>>(x, ln2_s + d * Dsz, ln2_b + d * Dsz, h);

        // mlp = gelu(h @ w1 + b1)   (4096 x 2048 x 512)
        mma_gemm<128,1><<<dim3((4 * Dsz) / 128, ROWS / 128), 256, SMEM128>>>(
            h, w1T + (size_t)d * Dsz * 4 * Dsz, b1 + (size_t)d * 4 * Dsz, nullptr,
            mlp, 4 * Dsz, Dsz);

        // x = x + mlp @ w2 + b2   (4096 x 512 x 2048)
        mma_gemm<64,2><<<dim3(Dsz / 64, ROWS / 128), 256, SMEM64>>>(
            mlp, w2T + (size_t)d * Dsz * 4 * Dsz, b2 + d * Dsz, x, x, Dsz, 4 * Dsz);
    }
}

// round 5
// speedup vs baseline: 4.1909x; 1.1531x over previous
#include <cuda_runtime.h>
#include <cuda_fp16.h>
#include <math.h>
#include <stdint.h>

#define Bsz   2
#define Tsz   2048
#define Dsz   512
#define Hn    8
#define HDm   64
#define Kw    16
#define NDEPTH 3
#define ROWS  (Bsz*Tsz)   // 4096

// ---------------- scratch (static device globals; no allocation) ----------------
__device__ __half g_h[ROWS * Dsz];
__device__ __half g_qkv[ROWS * 3 * Dsz];
__device__ __half g_o[ROWS * Dsz];
__device__ __half g_mlp[ROWS * 4 * Dsz];
// transposed fp16 weights ([N,K], K contiguous)
__device__ __half g_qkvwT[NDEPTH * 3 * Dsz * Dsz];
__device__ __half g_projwT[NDEPTH * Dsz * Dsz];
__device__ __half g_w1T[NDEPTH * 4 * Dsz * Dsz];
__device__ __half g_w2T[NDEPTH * Dsz * 4 * Dsz];

// ---------------- helpers ----------------------------------------------------------
__device__ __forceinline__ uint32_t smem_u32(const void* p) {
    uint32_t a;
    asm("{ .reg .u64 t; cvta.to.shared.u64 t, %1; cvt.u32.u64 %0, t; }" : "=r"(a) : "l"(p));
    return a;
}
__device__ __forceinline__ void cp16(uint32_t s, const void* g) {
    asm volatile("cp.async.cg.shared.global [%0], [%1], 16;" :: "r"(s), "l"(g));
}
__device__ __forceinline__ void ldsm4(uint32_t* r, uint32_t addr) {
    asm volatile("ldmatrix.sync.aligned.m8n8.x4.shared.b16 {%0,%1,%2,%3}, [%4];"
                 : "=r"(r[0]), "=r"(r[1]), "=r"(r[2]), "=r"(r[3]) : "r"(addr));
}
__device__ __forceinline__ void mma_f16(float* c, const uint32_t* a, const uint32_t* b) {
    asm volatile(
        "mma.sync.aligned.m16n8k16.row.col.f32.f16.f16.f32 "
        "{%0,%1,%2,%3}, {%4,%5,%6,%7}, {%8,%9}, {%0,%1,%2,%3};"
        : "+f"(c[0]), "+f"(c[1]), "+f"(c[2]), "+f"(c[3])
        : "r"(a[0]), "r"(a[1]), "r"(a[2]), "r"(a[3]), "r"(b[0]), "r"(b[1]));
}

// ---------------- fused weight prep: all 12 matrices, fp32 [K,N] -> fp16 [N,K] -----
// tiles per depth: qkv 48x16=768, proj 16x16=256, w1 64x16=1024, w2 16x64=1024 -> 3072
__global__ void prep_weights(const float* __restrict__ qkv_w, const float* __restrict__ proj_w,
                             const float* __restrict__ w1, const float* __restrict__ w2) {
    __shared__ float tile[32][33];
    int id = blockIdx.x;
    int d  = id / 3072;
    int r  = id % 3072;
    const float* in; __half* out; int R, C, t0;
    if (r < 768)       { in = qkv_w  + (size_t)d * Dsz * 3 * Dsz; out = g_qkvwT  + (size_t)d * 3 * Dsz * Dsz; R = Dsz;     C = 3 * Dsz; t0 = r; }
    else if (r < 1024) { in = proj_w + (size_t)d * Dsz * Dsz;     out = g_projwT + (size_t)d * Dsz * Dsz;     R = Dsz;     C = Dsz;     t0 = r - 768; }
    else if (r < 2048) { in = w1     + (size_t)d * Dsz * 4 * Dsz; out = g_w1T    + (size_t)d * 4 * Dsz * Dsz; R = Dsz;     C = 4 * Dsz; t0 = r - 1024; }
    else               { in = w2     + (size_t)d * 4 * Dsz * Dsz; out = g_w2T    + (size_t)d * Dsz * 4 * Dsz; R = 4 * Dsz; C = Dsz;     t0 = r - 2048; }
    int tpc = C / 32;
    int r0 = (t0 / tpc) * 32, c0 = (t0 % tpc) * 32;
    int tx = threadIdx.x, ty = threadIdx.y;   // (32, 8)
    #pragma unroll
    for (int i = 0; i < 32; i += 8)
        tile[ty + i][tx] = in[(size_t)(r0 + ty + i) * C + c0 + tx];
    __syncthreads();
    #pragma unroll
    for (int i = 0; i < 32; i += 8)
        out[(size_t)(c0 + ty + i) * R + r0 + tx] = __float2half(tile[tx][ty + i]);
}

// ---------------- LayerNorm (fp32 in, fp16 out), shuffle reduction ------------------
__global__ void ln_kernel(const float* __restrict__ x, const float* __restrict__ s,
                          const float* __restrict__ b, __half* __restrict__ out) {
    int row = blockIdx.x;
    int t = threadIdx.x;
    int w = t >> 5, lane = t & 31;
    const float* xr = x + (size_t)row * Dsz;
    float v0 = xr[t], v1 = xr[t + 256];

    float a = v0 + v1, q = v0 * v0 + v1 * v1;
    #pragma unroll
    for (int m = 16; m; m >>= 1) {
        a += __shfl_xor_sync(0xffffffffu, a, m);
        q += __shfl_xor_sync(0xffffffffu, q, m);
    }
    __shared__ float pa[8], pq[8];
    if (lane == 0) { pa[w] = a; pq[w] = q; }
    __syncthreads();
    float ta = 0.f, tq = 0.f;
    #pragma unroll
    for (int i = 0; i < 8; i++) { ta += pa[i]; tq += pq[i]; }
    float mean = ta * (1.0f / Dsz);
    float var  = tq * (1.0f / Dsz) - mean * mean;
    float inv  = rsqrtf(var + 1e-5f);
    __half* orow = out + (size_t)row * Dsz;
    orow[t]       = __float2half((v0 - mean) * inv * s[t]       + b[t]);
    orow[t + 256] = __float2half((v1 - mean) * inv * s[t + 256] + b[t + 256]);
}

// ---------------- Dilated sparse attention (half2 loads, fp32 math) -----------------
__global__ void attn_kernel(const __half* __restrict__ qkv, __half* __restrict__ o, int dil) {
    int gw   = (blockIdx.x * blockDim.x + threadIdx.x) >> 5;
    int lane = threadIdx.x & 31;
    int t  = gw & (Tsz - 1);
    int bh = gw >> 11;
    int h  = bh & (Hn - 1);
    int b  = bh >> 3;

    const __half2* qp = (const __half2*)(qkv + ((size_t)(b * Tsz + t)) * (3 * Dsz) + h * HDm);
    float2 qf = __half22float2(qp[lane]);
    int nv = t / dil + 1;
    if (nv > Kw) nv = Kw;

    float sc[Kw];
    #pragma unroll
    for (int s = 0; s < Kw; s++) {
        float e = -1e30f;
        if (s < nv) {
            int j = t - s * dil;
            const __half2* kp = (const __half2*)(qkv + ((size_t)(b * Tsz + j)) * (3 * Dsz) + Dsz + h * HDm);
            float2 kf = __half22float2(kp[lane]);
            float p = qf.x * kf.x + qf.y * kf.y;
            #pragma unroll
            for (int m = 16; m; m >>= 1) p += __shfl_xor_sync(0xffffffffu, p, m);
            e = p * 0.125f;
        }
        sc[s] = e;
    }
    float mx = sc[0];
    #pragma unroll
    for (int s = 1; s < Kw; s++) mx = fmaxf(mx, sc[s]);

    float denom = 0.f, o0 = 0.f, o1 = 0.f;
    #pragma unroll
    for (int s = 0; s < Kw; s++) {
        if (s < nv) {
            float w = expf(sc[s] - mx);
            denom += w;
            int j = t - s * dil;
            const __half2* vp = (const __half2*)(qkv + ((size_t)(b * Tsz + j)) * (3 * Dsz) + 2 * Dsz + h * HDm);
            float2 vf = __half22float2(vp[lane]);
            o0 += w * vf.x;
            o1 += w * vf.y;
        }
    }
    float r = 1.0f / denom;
    __half2* op = (__half2*)(o + ((size_t)(b * Tsz + t)) * Dsz + h * HDm);
    op[lane] = __floats2half2_rn(o0 * r, o1 * r);
}

// ---------------- fp16 mma.sync GEMM, 3-stage cp.async pipeline ----------------------
// C[M,N] = A[M,K] @ Bt[N,K]^T.  128 x BN_ x 32 tile, 256 threads (8 warps: 4M x 2N).
// Rows padded to 40 halves (conflict-free ldmatrix). One __syncthreads per chunk.
// EPI: 0 = store half, 1 = +bias + exact GELU -> half, 2 = +bias + residual -> float
template <int BN_, int EPI>
__global__ void __launch_bounds__(256)
mma_gemm(const __half* __restrict__ A, const __half* __restrict__ Bt,
         const float* __restrict__ bias, const float* __restrict__ res,
         void* __restrict__ Cv, int N, int K) {
    constexpr int BM = 128, BK = 32, S = 3;
    constexpr int RST = 40;                      // padded row stride (halves)
    constexpr int ABYTES = BM * RST * 2;         // 10240
    constexpr int BBYTES = BN_ * RST * 2;
    constexpr int WN = BN_ / 2;
    constexpr int NT = WN / 8;
    constexpr int NPAIR = NT / 2;
    constexpr int BITER = (BN_ * 4) / 256;       // B 16B-chunks per thread

    extern __shared__ char dsm[];
    const uint32_t sbase = smem_u32(dsm);
    const uint32_t bbase = sbase + S * ABYTES;

    const int tid  = threadIdx.x;
    const int w    = tid >> 5, lane = tid & 31;
    const int wm   = w & 3,   wn   = w >> 2;
    const int g    = lane >> 2, t4 = lane & 3;
    const int quad = lane >> 3, qr = lane & 7;
    const int bx   = blockIdx.x * BN_, by = blockIdx.y * BM;

    const __half* Ag[2]; uint32_t Asm[2];
    #pragma unroll
    for (int i = 0; i < 2; i++) {
        int e = tid + i * 256, row = e >> 2, seg = e & 3;
        Ag[i]  = A + (size_t)(by + row) * K + seg * 8;
        Asm[i] = sbase + (row * RST + seg * 8) * 2;
    }
    const __half* Bg[BITER]; uint32_t Bsm[BITER];
    #pragma unroll
    for (int i = 0; i < BITER; i++) {
        int e = tid + i * 256, row = e >> 2, seg = e & 3;
        Bg[i]  = Bt + (size_t)(bx + row) * K + seg * 8;
        Bsm[i] = bbase + (row * RST + seg * 8) * 2;
    }

    uint32_t aAddr[2], bAddr[NPAIR];
    #pragma unroll
    for (int mt = 0; mt < 2; mt++) {
        int row = wm * 32 + mt * 16 + (quad & 1) * 8 + qr;
        int col = (quad >> 1) * 8;
        aAddr[mt] = sbase + (row * RST + col) * 2;
    }
    #pragma unroll
    for (int p = 0; p < NPAIR; p++) {
        int row = wn * WN + p * 16 + (quad & 1) * 8 + qr;
        int col = (quad >> 1) * 8;
        bAddr[p] = bbase + (row * RST + col) * 2;
    }

    float acc[2][NT][4];
    #pragma unroll
    for (int i = 0; i < 2; i++)
        #pragma unroll
        for (int j = 0; j < NT; j++)
            #pragma unroll
            for (int q = 0; q < 4; q++) acc[i][j][q] = 0.f;

    const int nch = K / BK;   // >= 16

    // prologue: stages 0..S-2 <- chunks 0..S-2
    #pragma unroll
    for (int s = 0; s < S - 1; s++) {
        const int ko = s * BK;
        #pragma unroll
        for (int i = 0; i < 2; i++) cp16(Asm[i] + s * ABYTES, Ag[i] + ko);
        #pragma unroll
        for (int i = 0; i < BITER; i++) cp16(Bsm[i] + s * BBYTES, Bg[i] + ko);
        asm volatile("cp.async.commit_group;");
    }

    int cst = 0;            // stage holding chunk c
    int lst = (S - 1) % S;  // stage for chunk c+S-1

    for (int c = 0; c < nch; ++c) {
        asm volatile("cp.async.wait_group %0;" :: "n"(S - 2));
        __syncthreads();

        const int ls = c + S - 1;
        if (ls < nch) {
            const int ko = ls * BK;
            #pragma unroll
            for (int i = 0; i < 2; i++) cp16(Asm[i] + lst * ABYTES, Ag[i] + ko);
            #pragma unroll
            for (int i = 0; i < BITER; i++) cp16(Bsm[i] + lst * BBYTES, Bg[i] + ko);
        }
        asm volatile("cp.async.commit_group;");

        const uint32_t aOff = cst * ABYTES;
        const uint32_t bOff = cst * BBYTES;
        #pragma unroll
        for (int ks = 0; ks < 2; ks++) {
            const uint32_t kb = ks * 32;   // 16 halves
            uint32_t af[2][4];
            #pragma unroll
            for (int mt = 0; mt < 2; mt++) ldsm4(af[mt], aAddr[mt] + aOff + kb);
            uint32_t bf[NPAIR][4];
            #pragma unroll
            for (int p = 0; p < NPAIR; p++) ldsm4(bf[p], bAddr[p] + bOff + kb);
            #pragma unroll
            for (int mt = 0; mt < 2; mt++)
                #pragma unroll
                for (int p = 0; p < NPAIR; p++) {
                    uint32_t b0[2] = { bf[p][0], bf[p][2] };
                    uint32_t b1[2] = { bf[p][1], bf[p][3] };
                    mma_f16(acc[mt][2 * p],     af[mt], b0);
                    mma_f16(acc[mt][2 * p + 1], af[mt], b1);
                }
        }
        cst = (cst == S - 1) ? 0 : cst + 1;
        lst = (lst == S - 1) ? 0 : lst + 1;
    }

    // epilogue
    #pragma unroll
    for (int mt = 0; mt < 2; mt++) {
        const int r0 = by + wm * 32 + mt * 16 + g;
        #pragma unroll
        for (int nt = 0; nt < NT; nt++) {
            const int col = bx + wn * WN + nt * 8 + 2 * t4;
            float v0 = acc[mt][nt][0], v1 = acc[mt][nt][1];
            float v2 = acc[mt][nt][2], v3 = acc[mt][nt][3];
            if (EPI != 0) {
                float2 bb = *(const float2*)&bias[col];
                v0 += bb.x; v1 += bb.y; v2 += bb.x; v3 += bb.y;
            }
            if (EPI == 1) {
                v0 = 0.5f * v0 * (1.0f + erff(v0 * 0.70710678118654752f));
                v1 = 0.5f * v1 * (1.0f + erff(v1 * 0.70710678118654752f));
                v2 = 0.5f * v2 * (1.0f + erff(v2 * 0.70710678118654752f));
                v3 = 0.5f * v3 * (1.0f + erff(v3 * 0.70710678118654752f));
            }
            if (EPI == 2) {
                float* C = (float*)Cv;
                float2 ra = *(const float2*)&res[(size_t)r0 * N + col];
                float2 rb = *(const float2*)&res[(size_t)(r0 + 8) * N + col];
                float2 o01 = { v0 + ra.x, v1 + ra.y };
                float2 o23 = { v2 + rb.x, v3 + rb.y };
                *(float2*)&C[(size_t)r0 * N + col]       = o01;
                *(float2*)&C[(size_t)(r0 + 8) * N + col] = o23;
            } else {
                __half* C = (__half*)Cv;
                *(__half2*)&C[(size_t)r0 * N + col]       = __floats2half2_rn(v0, v1);
                *(__half2*)&C[(size_t)(r0 + 8) * N + col] = __floats2half2_rn(v2, v3);
            }
        }
    }
}

// ---------------- launcher -----------------------------------------------------------
#define SMEM128 (3*10240 + 3*10240)   // 61440
#define SMEM64  (3*10240 + 3*5120)    // 46080

extern "C" void kernel_launch(void* const* d_in, const int* in_sizes, int n_in,
                              void* d_out, int out_size) {
    const float* x_in   = (const float*)d_in[0];
    const float* ln1_s  = (const float*)d_in[1];
    const float* ln1_b  = (const float*)d_in[2];
    const float* qkv_w  = (const float*)d_in[3];
    const float* proj_w = (const float*)d_in[4];
    const float* proj_b = (const float*)d_in[5];
    const float* ln2_s  = (const float*)d_in[6];
    const float* ln2_b  = (const float*)d_in[7];
    const float* w1     = (const float*)d_in[8];
    const float* b1     = (const float*)d_in[9];
    const float* w2     = (const float*)d_in[10];
    const float* b2     = (const float*)d_in[11];

    float* x = (float*)d_out;

    __half *h, *qkv, *o, *mlp, *qkvT, *projT, *w1T, *w2T;
    cudaGetSymbolAddress((void**)&h,     g_h);
    cudaGetSymbolAddress((void**)&qkv,   g_qkv);
    cudaGetSymbolAddress((void**)&o,     g_o);
    cudaGetSymbolAddress((void**)&mlp,   g_mlp);
    cudaGetSymbolAddress((void**)&qkvT,  g_qkvwT);
    cudaGetSymbolAddress((void**)&projT, g_projwT);
    cudaGetSymbolAddress((void**)&w1T,   g_w1T);
    cudaGetSymbolAddress((void**)&w2T,   g_w2T);

    cudaFuncSetAttribute(mma_gemm<128,0>, cudaFuncAttributeMaxDynamicSharedMemorySize, SMEM128);
    cudaFuncSetAttribute(mma_gemm<128,1>, cudaFuncAttributeMaxDynamicSharedMemorySize, SMEM128);
    cudaFuncSetAttribute(mma_gemm<64,2>,  cudaFuncAttributeMaxDynamicSharedMemorySize, SMEM64);

    // all weight transposes in one launch (3*3072 tiles)
    prep_weights<<<NDEPTH * 3072, dim3(32, 8)>>>(qkv_w, proj_w, w1, w2);

    for (int d = 0; d < NDEPTH; d++) {
        int dil = 1 << d;
        const float* xr = (d == 0) ? x_in : x;   // residual stream source

        ln_kernel<<<ROWS, 256>>>(xr, ln1_s + d * Dsz, ln1_b + d * Dsz, h);

        // qkv = h @ qkv_w   (4096 x 1536 x 512)
        mma_gemm<128,0><<<dim3((3 * Dsz) / 128, ROWS / 128), 256, SMEM128>>>(
            h, qkvT + (size_t)d * 3 * Dsz * Dsz, nullptr, nullptr, qkv, 3 * Dsz, Dsz);

        attn_kernel<<<(ROWS * Hn) / 8, 256>>>(qkv, o, dil);

        // x = xr + o @ proj_w + proj_b   (4096 x 512 x 512)  — writes all of x
        mma_gemm<64,2><<<dim3(Dsz / 64, ROWS / 128), 256, SMEM64>>>(
            o, projT + (size_t)d * Dsz * Dsz, proj_b + d * Dsz, xr, x, Dsz, Dsz);

        ln_kernel<<<ROWS, 256>>>(x, ln2_s + d * Dsz, ln2_b + d * Dsz, h);

        // mlp = gelu(h @ w1 + b1)   (4096 x 2048 x 512)
        mma_gemm<128,1><<<dim3((4 * Dsz) / 128, ROWS / 128), 256, SMEM128>>>(
            h, w1T + (size_t)d * Dsz * 4 * Dsz, b1 + (size_t)d * 4 * Dsz, nullptr,
            mlp, 4 * Dsz, Dsz);

        // x = x + mlp @ w2 + b2   (4096 x 512 x 2048)
        mma_gemm<64,2><<<dim3(Dsz / 64, ROWS / 128), 256, SMEM64>>>(
            mlp, w2T + (size_t)d * Dsz * 4 * Dsz, b2 + d * Dsz, x, x, Dsz, 4 * Dsz);
    }
}

// round 6
// speedup vs baseline: 5.0834x; 1.2130x over previous
#include <cuda_runtime.h>
#include <cuda_fp16.h>
#include <math.h>
#include <stdint.h>

#define Bsz   2
#define Tsz   2048
#define Dsz   512
#define Hn    8
#define HDm   64
#define Kw    16
#define NDEPTH 3
#define ROWS  (Bsz*Tsz)   // 4096

// ---------------- scratch (static device globals; no allocation) ----------------
__device__ __half g_h[ROWS * Dsz];
__device__ __half g_qkv[ROWS * 3 * Dsz];
__device__ __half g_o[ROWS * Dsz];
__device__ __half g_mlp[ROWS * 4 * Dsz];
// transposed fp16 weights ([N,K], K contiguous)
__device__ __half g_qkvwT[NDEPTH * 3 * Dsz * Dsz];
__device__ __half g_projwT[NDEPTH * Dsz * Dsz];
__device__ __half g_w1T[NDEPTH * 4 * Dsz * Dsz];
__device__ __half g_w2T[NDEPTH * Dsz * 4 * Dsz];

// ---------------- helpers ----------------------------------------------------------
__device__ __forceinline__ uint32_t smem_u32(const void* p) {
    uint32_t a;
    asm("{ .reg .u64 t; cvta.to.shared.u64 t, %1; cvt.u32.u64 %0, t; }" : "=r"(a) : "l"(p));
    return a;
}
__device__ __forceinline__ void cp16(uint32_t s, const void* g) {
    asm volatile("cp.async.cg.shared.global [%0], [%1], 16;" :: "r"(s), "l"(g));
}
__device__ __forceinline__ void ldsm4(uint32_t* r, uint32_t addr) {
    asm volatile("ldmatrix.sync.aligned.m8n8.x4.shared.b16 {%0,%1,%2,%3}, [%4];"
                 : "=r"(r[0]), "=r"(r[1]), "=r"(r[2]), "=r"(r[3]) : "r"(addr));
}
__device__ __forceinline__ void mma_f16(float* c, const uint32_t* a, const uint32_t* b) {
    asm volatile(
        "mma.sync.aligned.m16n8k16.row.col.f32.f16.f16.f32 "
        "{%0,%1,%2,%3}, {%4,%5,%6,%7}, {%8,%9}, {%0,%1,%2,%3};"
        : "+f"(c[0]), "+f"(c[1]), "+f"(c[2]), "+f"(c[3])
        : "r"(a[0]), "r"(a[1]), "r"(a[2]), "r"(a[3]), "r"(b[0]), "r"(b[1]));
}

// ---------------- fused weight prep: all 12 matrices, fp32 [K,N] -> fp16 [N,K] -----
__global__ void prep_weights(const float* __restrict__ qkv_w, const float* __restrict__ proj_w,
                             const float* __restrict__ w1, const float* __restrict__ w2) {
    __shared__ float tile[32][33];
    int id = blockIdx.x;
    int d  = id / 3072;
    int r  = id % 3072;
    const float* in; __half* out; int R, C, t0;
    if (r < 768)       { in = qkv_w  + (size_t)d * Dsz * 3 * Dsz; out = g_qkvwT  + (size_t)d * 3 * Dsz * Dsz; R = Dsz;     C = 3 * Dsz; t0 = r; }
    else if (r < 1024) { in = proj_w + (size_t)d * Dsz * Dsz;     out = g_projwT + (size_t)d * Dsz * Dsz;     R = Dsz;     C = Dsz;     t0 = r - 768; }
    else if (r < 2048) { in = w1     + (size_t)d * Dsz * 4 * Dsz; out = g_w1T    + (size_t)d * 4 * Dsz * Dsz; R = Dsz;     C = 4 * Dsz; t0 = r - 1024; }
    else               { in = w2     + (size_t)d * 4 * Dsz * Dsz; out = g_w2T    + (size_t)d * Dsz * 4 * Dsz; R = 4 * Dsz; C = Dsz;     t0 = r - 2048; }
    int tpc = C / 32;
    int r0 = (t0 / tpc) * 32, c0 = (t0 % tpc) * 32;
    int tx = threadIdx.x, ty = threadIdx.y;   // (32, 8)
    #pragma unroll
    for (int i = 0; i < 32; i += 8)
        tile[ty + i][tx] = in[(size_t)(r0 + ty + i) * C + c0 + tx];
    __syncthreads();
    #pragma unroll
    for (int i = 0; i < 32; i += 8)
        out[(size_t)(c0 + ty + i) * R + r0 + tx] = __float2half(tile[tx][ty + i]);
}

// ---------------- LayerNorm (fp32 in, fp16 out), shuffle reduction ------------------
__global__ void ln_kernel(const float* __restrict__ x, const float* __restrict__ s,
                          const float* __restrict__ b, __half* __restrict__ out) {
    int row = blockIdx.x;
    int t = threadIdx.x;
    int w = t >> 5, lane = t & 31;
    const float* xr = x + (size_t)row * Dsz;
    float v0 = xr[t], v1 = xr[t + 256];

    float a = v0 + v1, q = v0 * v0 + v1 * v1;
    #pragma unroll
    for (int m = 16; m; m >>= 1) {
        a += __shfl_xor_sync(0xffffffffu, a, m);
        q += __shfl_xor_sync(0xffffffffu, q, m);
    }
    __shared__ float pa[8], pq[8];
    if (lane == 0) { pa[w] = a; pq[w] = q; }
    __syncthreads();
    float ta = 0.f, tq = 0.f;
    #pragma unroll
    for (int i = 0; i < 8; i++) { ta += pa[i]; tq += pq[i]; }
    float mean = ta * (1.0f / Dsz);
    float var  = tq * (1.0f / Dsz) - mean * mean;
    float inv  = rsqrtf(var + 1e-5f);
    __half* orow = out + (size_t)row * Dsz;
    orow[t]       = __float2half((v0 - mean) * inv * s[t]       + b[t]);
    orow[t + 256] = __float2half((v1 - mean) * inv * s[t + 256] + b[t + 256]);
}

// ---------------- Dilated sparse attention: 8 lanes/query, smem K/V tiles ----------
// block = 256 threads handles QT=64 queries of one (b,h). Keys for the tile span
// [q0 - 15*DIL, q0 + QT) -> NR rows staged in smem. Each lane owns 8 of 64 dims:
// score = LDS.128 + 8 FMA + 3 shuffles; V accum needs no shuffles.
#define QT 64
template <int DIL>
__global__ void __launch_bounds__(256)
attn_kernel(const __half* __restrict__ qkv, __half* __restrict__ o) {
    constexpr int NR = QT + (Kw - 1) * DIL;   // max rows staged
    __shared__ __half sk[NR * HDm];
    __shared__ __half sv[NR * HDm];

    const int tid = threadIdx.x;
    const int b   = blockIdx.y >> 3;
    const int h   = blockIdx.y & 7;
    const int q0  = blockIdx.x * QT;

    const int jlo   = max(0, q0 - (Kw - 1) * DIL);
    const int nrows = q0 + QT - jlo;

    // stage K/V rows [jlo, q0+QT) into smem (uint4 = 8 halves per chunk)
    const __half* kvbase = qkv + ((size_t)(b * Tsz + jlo)) * (3 * Dsz) + h * HDm;
    for (int idx = tid; idx < nrows * 8; idx += 256) {
        int row = idx >> 3, seg = idx & 7;
        const __half* src = kvbase + (size_t)row * (3 * Dsz) + seg * 8;
        *(uint4*)&sk[row * HDm + seg * 8] = *(const uint4*)(src + Dsz);
        *(uint4*)&sv[row * HDm + seg * 8] = *(const uint4*)(src + 2 * Dsz);
    }
    __syncthreads();

    const int l8 = tid & 7;          // lane within query group (owns dims l8*8..l8*8+7)
    #pragma unroll
    for (int pass = 0; pass < 2; pass++) {
        const int q = q0 + pass * 32 + (tid >> 3);

        // load q fragment (8 dims)
        uint4 qv = *(const uint4*)(qkv + ((size_t)(b * Tsz + q)) * (3 * Dsz) + h * HDm + l8 * 8);
        float2 qf[4];
        {
            const __half2* qh = (const __half2*)&qv;
            #pragma unroll
            for (int i = 0; i < 4; i++) qf[i] = __half22float2(qh[i]);
        }

        int nv = q / DIL + 1;
        if (nv > Kw) nv = Kw;

        float sc[Kw];
        #pragma unroll
        for (int s = 0; s < Kw; s++) {
            float e = -1e30f;
            if (s < nv) {
                int r = q - s * DIL - jlo;
                uint4 kv4 = *(const uint4*)&sk[r * HDm + l8 * 8];
                const __half2* kh = (const __half2*)&kv4;
                float p = 0.f;
                #pragma unroll
                for (int i = 0; i < 4; i++) {
                    float2 kf = __half22float2(kh[i]);
                    p += qf[i].x * kf.x + qf[i].y * kf.y;
                }
                p += __shfl_xor_sync(0xffffffffu, p, 4);
                p += __shfl_xor_sync(0xffffffffu, p, 2);
                p += __shfl_xor_sync(0xffffffffu, p, 1);
                e = p * 0.125f;
            }
            sc[s] = e;
        }
        float mx = sc[0];
        #pragma unroll
        for (int s = 1; s < Kw; s++) mx = fmaxf(mx, sc[s]);

        float denom = 0.f;
        float oa[8] = {0.f, 0.f, 0.f, 0.f, 0.f, 0.f, 0.f, 0.f};
        #pragma unroll
        for (int s = 0; s < Kw; s++) {
            if (s < nv) {
                float wgt = expf(sc[s] - mx);
                denom += wgt;
                int r = q - s * DIL - jlo;
                uint4 vv4 = *(const uint4*)&sv[r * HDm + l8 * 8];
                const __half2* vh = (const __half2*)&vv4;
                #pragma unroll
                for (int i = 0; i < 4; i++) {
                    float2 vf = __half22float2(vh[i]);
                    oa[2 * i]     += wgt * vf.x;
                    oa[2 * i + 1] += wgt * vf.y;
                }
            }
        }
        float rcp = 1.0f / denom;
        __half2 oh[4];
        #pragma unroll
        for (int i = 0; i < 4; i++)
            oh[i] = __floats2half2_rn(oa[2 * i] * rcp, oa[2 * i + 1] * rcp);
        *(uint4*)(o + ((size_t)(b * Tsz + q)) * Dsz + h * HDm + l8 * 8) = *(uint4*)oh;
    }
}

// ---------------- fp16 mma.sync GEMM, S-stage cp.async pipeline ----------------------
// C[M,N] = A[M,K] @ Bt[N,K]^T.  128 x BN_ x 32 tile, 256 threads (8 warps: 4M x 2N).
// EPI: 0 = store half, 1 = +bias + exact GELU -> half, 2 = +bias + residual -> float
template <int BN_, int EPI, int S>
__global__ void __launch_bounds__(256)
mma_gemm(const __half* __restrict__ A, const __half* __restrict__ Bt,
         const float* __restrict__ bias, const float* __restrict__ res,
         void* __restrict__ Cv, int N, int K) {
    constexpr int BM = 128, BK = 32;
    constexpr int RST = 40;                      // padded row stride (halves)
    constexpr int ABYTES = BM * RST * 2;         // 10240
    constexpr int BBYTES = BN_ * RST * 2;
    constexpr int WN = BN_ / 2;
    constexpr int NT = WN / 8;
    constexpr int NPAIR = NT / 2;
    constexpr int BITER = (BN_ * 4) / 256;

    extern __shared__ char dsm[];
    const uint32_t sbase = smem_u32(dsm);
    const uint32_t bbase = sbase + S * ABYTES;

    const int tid  = threadIdx.x;
    const int w    = tid >> 5, lane = tid & 31;
    const int wm   = w & 3,   wn   = w >> 2;
    const int g    = lane >> 2, t4 = lane & 3;
    const int quad = lane >> 3, qr = lane & 7;
    const int bx   = blockIdx.x * BN_, by = blockIdx.y * BM;

    const __half* Ag[2]; uint32_t Asm[2];
    #pragma unroll
    for (int i = 0; i < 2; i++) {
        int e = tid + i * 256, row = e >> 2, seg = e & 3;
        Ag[i]  = A + (size_t)(by + row) * K + seg * 8;
        Asm[i] = sbase + (row * RST + seg * 8) * 2;
    }
    const __half* Bg[BITER]; uint32_t Bsm[BITER];
    #pragma unroll
    for (int i = 0; i < BITER; i++) {
        int e = tid + i * 256, row = e >> 2, seg = e & 3;
        Bg[i]  = Bt + (size_t)(bx + row) * K + seg * 8;
        Bsm[i] = bbase + (row * RST + seg * 8) * 2;
    }

    uint32_t aAddr[2], bAddr[NPAIR];
    #pragma unroll
    for (int mt = 0; mt < 2; mt++) {
        int row = wm * 32 + mt * 16 + (quad & 1) * 8 + qr;
        int col = (quad >> 1) * 8;
        aAddr[mt] = sbase + (row * RST + col) * 2;
    }
    #pragma unroll
    for (int p = 0; p < NPAIR; p++) {
        int row = wn * WN + p * 16 + (quad & 1) * 8 + qr;
        int col = (quad >> 1) * 8;
        bAddr[p] = bbase + (row * RST + col) * 2;
    }

    float acc[2][NT][4];
    #pragma unroll
    for (int i = 0; i < 2; i++)
        #pragma unroll
        for (int j = 0; j < NT; j++)
            #pragma unroll
            for (int q = 0; q < 4; q++) acc[i][j][q] = 0.f;

    const int nch = K / BK;

    #pragma unroll
    for (int s = 0; s < S - 1; s++) {
        const int ko = s * BK;
        #pragma unroll
        for (int i = 0; i < 2; i++) cp16(Asm[i] + s * ABYTES, Ag[i] + ko);
        #pragma unroll
        for (int i = 0; i < BITER; i++) cp16(Bsm[i] + s * BBYTES, Bg[i] + ko);
        asm volatile("cp.async.commit_group;");
    }

    int cst = 0;
    int lst = S - 1;

    for (int c = 0; c < nch; ++c) {
        asm volatile("cp.async.wait_group %0;" :: "n"(S - 2));
        __syncthreads();

        const int ls = c + S - 1;
        if (ls < nch) {
            const int ko = ls * BK;
            #pragma unroll
            for (int i = 0; i < 2; i++) cp16(Asm[i] + lst * ABYTES, Ag[i] + ko);
            #pragma unroll
            for (int i = 0; i < BITER; i++) cp16(Bsm[i] + lst * BBYTES, Bg[i] + ko);
        }
        asm volatile("cp.async.commit_group;");

        const uint32_t aOff = cst * ABYTES;
        const uint32_t bOff = cst * BBYTES;
        #pragma unroll
        for (int ks = 0; ks < 2; ks++) {
            const uint32_t kb = ks * 32;
            uint32_t af[2][4];
            #pragma unroll
            for (int mt = 0; mt < 2; mt++) ldsm4(af[mt], aAddr[mt] + aOff + kb);
            uint32_t bf[NPAIR][4];
            #pragma unroll
            for (int p = 0; p < NPAIR; p++) ldsm4(bf[p], bAddr[p] + bOff + kb);
            #pragma unroll
            for (int mt = 0; mt < 2; mt++)
                #pragma unroll
                for (int p = 0; p < NPAIR; p++) {
                    uint32_t b0[2] = { bf[p][0], bf[p][2] };
                    uint32_t b1[2] = { bf[p][1], bf[p][3] };
                    mma_f16(acc[mt][2 * p],     af[mt], b0);
                    mma_f16(acc[mt][2 * p + 1], af[mt], b1);
                }
        }
        cst = (cst == S - 1) ? 0 : cst + 1;
        lst = (lst == S - 1) ? 0 : lst + 1;
    }

    #pragma unroll
    for (int mt = 0; mt < 2; mt++) {
        const int r0 = by + wm * 32 + mt * 16 + g;
        #pragma unroll
        for (int nt = 0; nt < NT; nt++) {
            const int col = bx + wn * WN + nt * 8 + 2 * t4;
            float v0 = acc[mt][nt][0], v1 = acc[mt][nt][1];
            float v2 = acc[mt][nt][2], v3 = acc[mt][nt][3];
            if (EPI != 0) {
                float2 bb = *(const float2*)&bias[col];
                v0 += bb.x; v1 += bb.y; v2 += bb.x; v3 += bb.y;
            }
            if (EPI == 1) {
                v0 = 0.5f * v0 * (1.0f + erff(v0 * 0.70710678118654752f));
                v1 = 0.5f * v1 * (1.0f + erff(v1 * 0.70710678118654752f));
                v2 = 0.5f * v2 * (1.0f + erff(v2 * 0.70710678118654752f));
                v3 = 0.5f * v3 * (1.0f + erff(v3 * 0.70710678118654752f));
            }
            if (EPI == 2) {
                float* C = (float*)Cv;
                float2 ra = *(const float2*)&res[(size_t)r0 * N + col];
                float2 rb = *(const float2*)&res[(size_t)(r0 + 8) * N + col];
                float2 o01 = { v0 + ra.x, v1 + ra.y };
                float2 o23 = { v2 + rb.x, v3 + rb.y };
                *(float2*)&C[(size_t)r0 * N + col]       = o01;
                *(float2*)&C[(size_t)(r0 + 8) * N + col] = o23;
            } else {
                __half* C = (__half*)Cv;
                *(__half2*)&C[(size_t)r0 * N + col]       = __floats2half2_rn(v0, v1);
                *(__half2*)&C[(size_t)(r0 + 8) * N + col] = __floats2half2_rn(v2, v3);
            }
        }
    }
}

// ---------------- launcher -----------------------------------------------------------
#define SMEM128 (3*10240 + 3*10240)   // 61440 (S=3, BN=128)
#define SMEM64  (4*10240 + 4*5120)    // 61440 (S=4, BN=64)

extern "C" void kernel_launch(void* const* d_in, const int* in_sizes, int n_in,
                              void* d_out, int out_size) {
    const float* x_in   = (const float*)d_in[0];
    const float* ln1_s  = (const float*)d_in[1];
    const float* ln1_b  = (const float*)d_in[2];
    const float* qkv_w  = (const float*)d_in[3];
    const float* proj_w = (const float*)d_in[4];
    const float* proj_b = (const float*)d_in[5];
    const float* ln2_s  = (const float*)d_in[6];
    const float* ln2_b  = (const float*)d_in[7];
    const float* w1     = (const float*)d_in[8];
    const float* b1     = (const float*)d_in[9];
    const float* w2     = (const float*)d_in[10];
    const float* b2     = (const float*)d_in[11];

    float* x = (float*)d_out;

    __half *h, *qkv, *o, *mlp, *qkvT, *projT, *w1T, *w2T;
    cudaGetSymbolAddress((void**)&h,     g_h);
    cudaGetSymbolAddress((void**)&qkv,   g_qkv);
    cudaGetSymbolAddress((void**)&o,     g_o);
    cudaGetSymbolAddress((void**)&mlp,   g_mlp);
    cudaGetSymbolAddress((void**)&qkvT,  g_qkvwT);
    cudaGetSymbolAddress((void**)&projT, g_projwT);
    cudaGetSymbolAddress((void**)&w1T,   g_w1T);
    cudaGetSymbolAddress((void**)&w2T,   g_w2T);

    cudaFuncSetAttribute((const void*)mma_gemm<128,0,3>, cudaFuncAttributeMaxDynamicSharedMemorySize, SMEM128);
    cudaFuncSetAttribute((const void*)mma_gemm<128,1,3>, cudaFuncAttributeMaxDynamicSharedMemorySize, SMEM128);
    cudaFuncSetAttribute((const void*)mma_gemm<64,2,4>,  cudaFuncAttributeMaxDynamicSharedMemorySize, SMEM64);

    prep_weights<<<NDEPTH * 3072, dim3(32, 8)>>>(qkv_w, proj_w, w1, w2);

    for (int d = 0; d < NDEPTH; d++) {
        const float* xr = (d == 0) ? x_in : x;

        ln_kernel<<<ROWS, 256>>>(xr, ln1_s + d * Dsz, ln1_b + d * Dsz, h);

        // qkv = h @ qkv_w   (4096 x 1536 x 512)
        mma_gemm<128,0,3><<<dim3((3 * Dsz) / 128, ROWS / 128), 256, SMEM128>>>(
            h, qkvT + (size_t)d * 3 * Dsz * Dsz, nullptr, nullptr, qkv, 3 * Dsz, Dsz);

        // sparse dilated attention
        dim3 agrid(Tsz / QT, Bsz * Hn);
        if (d == 0)      attn_kernel<1><<<agrid, 256>>>(qkv, o);
        else if (d == 1) attn_kernel<2><<<agrid, 256>>>(qkv, o);
        else             attn_kernel<4><<<agrid, 256>>>(qkv, o);

        // x = xr + o @ proj_w + proj_b   (4096 x 512 x 512)
        mma_gemm<64,2,4><<<dim3(Dsz / 64, ROWS / 128), 256, SMEM64>>>(
            o, projT + (size_t)d * Dsz * Dsz, proj_b + d * Dsz, xr, x, Dsz, Dsz);

        ln_kernel<<<ROWS, 256>>>(x, ln2_s + d * Dsz, ln2_b + d * Dsz, h);

        // mlp = gelu(h @ w1 + b1)   (4096 x 2048 x 512)
        mma_gemm<128,1,3><<<dim3((4 * Dsz) / 128, ROWS / 128), 256, SMEM128>>>(
            h, w1T + (size_t)d * Dsz * 4 * Dsz, b1 + (size_t)d * 4 * Dsz, nullptr,
            mlp, 4 * Dsz, Dsz);

        // x = x + mlp @ w2 + b2   (4096 x 512 x 2048)
        mma_gemm<64,2,4><<<dim3(Dsz / 64, ROWS / 128), 256, SMEM64>>>(
            mlp, w2T + (size_t)d * Dsz * 4 * Dsz, b2 + d * Dsz, x, x, Dsz, 4 * Dsz);
    }
}

// round 7
// speedup vs baseline: 5.5698x; 1.0957x over previous
#include <cuda_runtime.h>
#include <cuda_fp16.h>
#include <math.h>
#include <stdint.h>

#define Bsz   2
#define Tsz   2048
#define Dsz   512
#define Hn    8
#define HDm   64
#define Kw    16
#define NDEPTH 3
#define ROWS  (Bsz*Tsz)   // 4096

// ---------------- scratch (static device globals; no allocation) ----------------
__device__ __half g_h[ROWS * Dsz];
__device__ __half g_qkv[ROWS * 3 * Dsz];
__device__ __half g_o[ROWS * Dsz];
__device__ __half g_mlp[ROWS * 4 * Dsz];
// transposed fp16 weights ([N,K], K contiguous)
__device__ __half g_qkvwT[NDEPTH * 3 * Dsz * Dsz];
__device__ __half g_projwT[NDEPTH * Dsz * Dsz];
__device__ __half g_w1T[NDEPTH * 4 * Dsz * Dsz];
__device__ __half g_w2T[NDEPTH * Dsz * 4 * Dsz];

// ---------------- helpers ----------------------------------------------------------
__device__ __forceinline__ uint32_t smem_u32(const void* p) {
    uint32_t a;
    asm("{ .reg .u64 t; cvta.to.shared.u64 t, %1; cvt.u32.u64 %0, t; }" : "=r"(a) : "l"(p));
    return a;
}
__device__ __forceinline__ void cp16(uint32_t s, const void* g) {
    asm volatile("cp.async.cg.shared.global [%0], [%1], 16;" :: "r"(s), "l"(g));
}
__device__ __forceinline__ void ldsm4(uint32_t* r, uint32_t addr) {
    asm volatile("ldmatrix.sync.aligned.m8n8.x4.shared.b16 {%0,%1,%2,%3}, [%4];"
                 : "=r"(r[0]), "=r"(r[1]), "=r"(r[2]), "=r"(r[3]) : "r"(addr));
}
__device__ __forceinline__ void mma_f16(float* c, const uint32_t* a, const uint32_t* b) {
    asm volatile(
        "mma.sync.aligned.m16n8k16.row.col.f32.f16.f16.f32 "
        "{%0,%1,%2,%3}, {%4,%5,%6,%7}, {%8,%9}, {%0,%1,%2,%3};"
        : "+f"(c[0]), "+f"(c[1]), "+f"(c[2]), "+f"(c[3])
        : "r"(a[0]), "r"(a[1]), "r"(a[2]), "r"(a[3]), "r"(b[0]), "r"(b[1]));
}

// ---------------- fused weight prep: all 12 matrices, fp32 [K,N] -> fp16 [N,K] -----
__global__ void prep_weights(const float* __restrict__ qkv_w, const float* __restrict__ proj_w,
                             const float* __restrict__ w1, const float* __restrict__ w2) {
    __shared__ float tile[32][33];
    int id = blockIdx.x;
    int d  = id / 3072;
    int r  = id % 3072;
    const float* in; __half* out; int R, C, t0;
    if (r < 768)       { in = qkv_w  + (size_t)d * Dsz * 3 * Dsz; out = g_qkvwT  + (size_t)d * 3 * Dsz * Dsz; R = Dsz;     C = 3 * Dsz; t0 = r; }
    else if (r < 1024) { in = proj_w + (size_t)d * Dsz * Dsz;     out = g_projwT + (size_t)d * Dsz * Dsz;     R = Dsz;     C = Dsz;     t0 = r - 768; }
    else if (r < 2048) { in = w1     + (size_t)d * Dsz * 4 * Dsz; out = g_w1T    + (size_t)d * 4 * Dsz * Dsz; R = Dsz;     C = 4 * Dsz; t0 = r - 1024; }
    else               { in = w2     + (size_t)d * 4 * Dsz * Dsz; out = g_w2T    + (size_t)d * Dsz * 4 * Dsz; R = 4 * Dsz; C = Dsz;     t0 = r - 2048; }
    int tpc = C / 32;
    int r0 = (t0 / tpc) * 32, c0 = (t0 % tpc) * 32;
    int tx = threadIdx.x, ty = threadIdx.y;   // (32, 8)
    #pragma unroll
    for (int i = 0; i < 32; i += 8)
        tile[ty + i][tx] = in[(size_t)(r0 + ty + i) * C + c0 + tx];
    __syncthreads();
    #pragma unroll
    for (int i = 0; i < 32; i += 8)
        out[(size_t)(c0 + ty + i) * R + r0 + tx] = __float2half(tile[tx][ty + i]);
}

// ---------------- LayerNorm (fp32 in, fp16 out), shuffle reduction ------------------
__global__ void ln_kernel(const float* __restrict__ x, const float* __restrict__ s,
                          const float* __restrict__ b, __half* __restrict__ out) {
    int row = blockIdx.x;
    int t = threadIdx.x;
    int w = t >> 5, lane = t & 31;
    const float* xr = x + (size_t)row * Dsz;
    float v0 = xr[t], v1 = xr[t + 256];

    float a = v0 + v1, q = v0 * v0 + v1 * v1;
    #pragma unroll
    for (int m = 16; m; m >>= 1) {
        a += __shfl_xor_sync(0xffffffffu, a, m);
        q += __shfl_xor_sync(0xffffffffu, q, m);
    }
    __shared__ float pa[8], pq[8];
    if (lane == 0) { pa[w] = a; pq[w] = q; }
    __syncthreads();
    float ta = 0.f, tq = 0.f;
    #pragma unroll
    for (int i = 0; i < 8; i++) { ta += pa[i]; tq += pq[i]; }
    float mean = ta * (1.0f / Dsz);
    float var  = tq * (1.0f / Dsz) - mean * mean;
    float inv  = rsqrtf(var + 1e-5f);
    __half* orow = out + (size_t)row * Dsz;
    orow[t]       = __float2half((v0 - mean) * inv * s[t]       + b[t]);
    orow[t + 256] = __float2half((v1 - mean) * inv * s[t + 256] + b[t + 256]);
}

// ---------------- Dilated sparse attention: QT=32 queries/block, 8 lanes/query ------
#define QT 32
template <int DIL>
__global__ void __launch_bounds__(256)
attn_kernel(const __half* __restrict__ qkv, __half* __restrict__ o) {
    constexpr int NR = QT + (Kw - 1) * DIL;   // rows staged (max 92 @ DIL=4)
    __shared__ __half sk[NR * HDm];
    __shared__ __half sv[NR * HDm];

    const int tid = threadIdx.x;
    const int b   = blockIdx.y >> 3;
    const int h   = blockIdx.y & 7;
    const int q0  = blockIdx.x * QT;

    const int jlo   = max(0, q0 - (Kw - 1) * DIL);
    const int nrows = q0 + QT - jlo;

    // stage K/V rows [jlo, q0+QT) into smem (uint4 = 8 halves per chunk)
    const __half* kvbase = qkv + ((size_t)(b * Tsz + jlo)) * (3 * Dsz) + h * HDm;
    for (int idx = tid; idx < nrows * 8; idx += 256) {
        int row = idx >> 3, seg = idx & 7;
        const __half* src = kvbase + (size_t)row * (3 * Dsz) + seg * 8;
        *(uint4*)&sk[row * HDm + seg * 8] = *(const uint4*)(src + Dsz);
        *(uint4*)&sv[row * HDm + seg * 8] = *(const uint4*)(src + 2 * Dsz);
    }
    __syncthreads();

    const int l8 = tid & 7;            // owns dims l8*8 .. l8*8+7
    const int q  = q0 + (tid >> 3);    // 32 queries x 8 lanes

    uint4 qv = *(const uint4*)(qkv + ((size_t)(b * Tsz + q)) * (3 * Dsz) + h * HDm + l8 * 8);
    float2 qf[4];
    {
        const __half2* qh = (const __half2*)&qv;
        #pragma unroll
        for (int i = 0; i < 4; i++) qf[i] = __half22float2(qh[i]);
    }

    int nv = q / DIL + 1;
    if (nv > Kw) nv = Kw;

    float sc[Kw];
    #pragma unroll
    for (int s = 0; s < Kw; s++) {
        float e = -1e30f;
        if (s < nv) {
            int r = q - s * DIL - jlo;
            uint4 kv4 = *(const uint4*)&sk[r * HDm + l8 * 8];
            const __half2* kh = (const __half2*)&kv4;
            float p = 0.f;
            #pragma unroll
            for (int i = 0; i < 4; i++) {
                float2 kf = __half22float2(kh[i]);
                p += qf[i].x * kf.x + qf[i].y * kf.y;
            }
            p += __shfl_xor_sync(0xffffffffu, p, 4);
            p += __shfl_xor_sync(0xffffffffu, p, 2);
            p += __shfl_xor_sync(0xffffffffu, p, 1);
            e = p * 0.125f;
        }
        sc[s] = e;
    }
    float mx = sc[0];
    #pragma unroll
    for (int s = 1; s < Kw; s++) mx = fmaxf(mx, sc[s]);

    float denom = 0.f;
    float oa[8] = {0.f, 0.f, 0.f, 0.f, 0.f, 0.f, 0.f, 0.f};
    #pragma unroll
    for (int s = 0; s < Kw; s++) {
        if (s < nv) {
            float wgt = expf(sc[s] - mx);
            denom += wgt;
            int r = q - s * DIL - jlo;
            uint4 vv4 = *(const uint4*)&sv[r * HDm + l8 * 8];
            const __half2* vh = (const __half2*)&vv4;
            #pragma unroll
            for (int i = 0; i < 4; i++) {
                float2 vf = __half22float2(vh[i]);
                oa[2 * i]     += wgt * vf.x;
                oa[2 * i + 1] += wgt * vf.y;
            }
        }
    }
    float rcp = 1.0f / denom;
    __half2 oh[4];
    #pragma unroll
    for (int i = 0; i < 4; i++)
        oh[i] = __floats2half2_rn(oa[2 * i] * rcp, oa[2 * i + 1] * rcp);
    *(uint4*)(o + ((size_t)(b * Tsz + q)) * Dsz + h * HDm + l8 * 8) = *(uint4*)oh;
}

// ---------------- fp16 mma.sync GEMM, BK=64, double-buffered -------------------------
// C[M,N] = A[M,K] @ Bt[N,K]^T.  128 x BN_ x 64 tile, 256 threads (8 warps: 4M x 2N).
// Rows padded to 72 halves (conflict-free ldmatrix). Load c+1 overlaps compute c.
// EPI: 0 = store half, 1 = +bias + exact GELU -> half, 2 = +bias + residual -> float
template <int BN_, int EPI>
__global__ void __launch_bounds__(256)
mma_gemm(const __half* __restrict__ A, const __half* __restrict__ Bt,
         const float* __restrict__ bias, const float* __restrict__ res,
         void* __restrict__ Cv, int N, int K) {
    constexpr int BM = 128, BK = 64;
    constexpr int RST = 72;                      // padded row stride (halves)
    constexpr int ABYTES = BM * RST * 2;         // 18432
    constexpr int BBYTES = BN_ * RST * 2;
    constexpr int WN = BN_ / 2;
    constexpr int NT = WN / 8;
    constexpr int NPAIR = NT / 2;
    constexpr int AITER = (BM * BK / 8) / 256;   // 4
    constexpr int BITER = (BN_ * BK / 8) / 256;  // 4 or 2

    extern __shared__ char dsm[];
    const uint32_t sbase = smem_u32(dsm);
    const uint32_t bbase = sbase + 2 * ABYTES;

    const int tid  = threadIdx.x;
    const int w    = tid >> 5, lane = tid & 31;
    const int wm   = w & 3,   wn   = w >> 2;
    const int g    = lane >> 2, t4 = lane & 3;
    const int quad = lane >> 3, qr = lane & 7;
    const int bx   = blockIdx.x * BN_, by = blockIdx.y * BM;

    const __half* Ag[AITER]; uint32_t Asm[AITER];
    #pragma unroll
    for (int i = 0; i < AITER; i++) {
        int e = tid + i * 256, row = e >> 3, seg = e & 7;
        Ag[i]  = A + (size_t)(by + row) * K + seg * 8;
        Asm[i] = sbase + (row * RST + seg * 8) * 2;
    }
    const __half* Bg[BITER]; uint32_t Bsm[BITER];
    #pragma unroll
    for (int i = 0; i < BITER; i++) {
        int e = tid + i * 256, row = e >> 3, seg = e & 7;
        Bg[i]  = Bt + (size_t)(bx + row) * K + seg * 8;
        Bsm[i] = bbase + (row * RST + seg * 8) * 2;
    }

    uint32_t aAddr[2], bAddr[NPAIR];
    #pragma unroll
    for (int mt = 0; mt < 2; mt++) {
        int row = wm * 32 + mt * 16 + (quad & 1) * 8 + qr;
        int col = (quad >> 1) * 8;
        aAddr[mt] = sbase + (row * RST + col) * 2;
    }
    #pragma unroll
    for (int p = 0; p < NPAIR; p++) {
        int row = wn * WN + p * 16 + (quad & 1) * 8 + qr;
        int col = (quad >> 1) * 8;
        bAddr[p] = bbase + (row * RST + col) * 2;
    }

    float acc[2][NT][4];
    #pragma unroll
    for (int i = 0; i < 2; i++)
        #pragma unroll
        for (int j = 0; j < NT; j++)
            #pragma unroll
            for (int q = 0; q < 4; q++) acc[i][j][q] = 0.f;

    const int nch = K / BK;   // >= 8

    // prologue: chunk 0 -> buffer 0
    #pragma unroll
    for (int i = 0; i < AITER; i++) cp16(Asm[i], Ag[i]);
    #pragma unroll
    for (int i = 0; i < BITER; i++) cp16(Bsm[i], Bg[i]);
    asm volatile("cp.async.commit_group;");

    for (int c = 0; c < nch; ++c) {
        const int buf = c & 1;
        // drain chunk c, then barrier (also protects buf^1 from the new issue below)
        asm volatile("cp.async.wait_group 0;");
        __syncthreads();

        if (c + 1 < nch) {
            const int nb = buf ^ 1;
            const int ko = (c + 1) * BK;
            #pragma unroll
            for (int i = 0; i < AITER; i++) cp16(Asm[i] + nb * ABYTES, Ag[i] + ko);
            #pragma unroll
            for (int i = 0; i < BITER; i++) cp16(Bsm[i] + nb * BBYTES, Bg[i] + ko);
            asm volatile("cp.async.commit_group;");
        }

        const uint32_t aOff = buf * ABYTES;
        const uint32_t bOff = buf * BBYTES;
        #pragma unroll
        for (int ks = 0; ks < 4; ks++) {
            const uint32_t kb = ks * 32;   // 16 halves per k-step
            uint32_t af[2][4];
            #pragma unroll
            for (int mt = 0; mt < 2; mt++) ldsm4(af[mt], aAddr[mt] + aOff + kb);
            uint32_t bf[NPAIR][4];
            #pragma unroll
            for (int p = 0; p < NPAIR; p++) ldsm4(bf[p], bAddr[p] + bOff + kb);
            #pragma unroll
            for (int mt = 0; mt < 2; mt++)
                #pragma unroll
                for (int p = 0; p < NPAIR; p++) {
                    uint32_t b0[2] = { bf[p][0], bf[p][2] };
                    uint32_t b1[2] = { bf[p][1], bf[p][3] };
                    mma_f16(acc[mt][2 * p],     af[mt], b0);
                    mma_f16(acc[mt][2 * p + 1], af[mt], b1);
                }
        }
    }

    // epilogue
    #pragma unroll
    for (int mt = 0; mt < 2; mt++) {
        const int r0 = by + wm * 32 + mt * 16 + g;
        #pragma unroll
        for (int nt = 0; nt < NT; nt++) {
            const int col = bx + wn * WN + nt * 8 + 2 * t4;
            float v0 = acc[mt][nt][0], v1 = acc[mt][nt][1];
            float v2 = acc[mt][nt][2], v3 = acc[mt][nt][3];
            if (EPI != 0) {
                float2 bb = *(const float2*)&bias[col];
                v0 += bb.x; v1 += bb.y; v2 += bb.x; v3 += bb.y;
            }
            if (EPI == 1) {
                v0 = 0.5f * v0 * (1.0f + erff(v0 * 0.70710678118654752f));
                v1 = 0.5f * v1 * (1.0f + erff(v1 * 0.70710678118654752f));
                v2 = 0.5f * v2 * (1.0f + erff(v2 * 0.70710678118654752f));
                v3 = 0.5f * v3 * (1.0f + erff(v3 * 0.70710678118654752f));
            }
            if (EPI == 2) {
                float* C = (float*)Cv;
                float2 ra = *(const float2*)&res[(size_t)r0 * N + col];
                float2 rb = *(const float2*)&res[(size_t)(r0 + 8) * N + col];
                float2 o01 = { v0 + ra.x, v1 + ra.y };
                float2 o23 = { v2 + rb.x, v3 + rb.y };
                *(float2*)&C[(size_t)r0 * N + col]       = o01;
                *(float2*)&C[(size_t)(r0 + 8) * N + col] = o23;
            } else {
                __half* C = (__half*)Cv;
                *(__half2*)&C[(size_t)r0 * N + col]       = __floats2half2_rn(v0, v1);
                *(__half2*)&C[(size_t)(r0 + 8) * N + col] = __floats2half2_rn(v2, v3);
            }
        }
    }
}

// ---------------- launcher -----------------------------------------------------------
#define SMEM128 (2*18432 + 2*18432)   // 73728 (BN=128)
#define SMEM64  (2*18432 + 2*9216)    // 55296 (BN=64)

extern "C" void kernel_launch(void* const* d_in, const int* in_sizes, int n_in,
                              void* d_out, int out_size) {
    const float* x_in   = (const float*)d_in[0];
    const float* ln1_s  = (const float*)d_in[1];
    const float* ln1_b  = (const float*)d_in[2];
    const float* qkv_w  = (const float*)d_in[3];
    const float* proj_w = (const float*)d_in[4];
    const float* proj_b = (const float*)d_in[5];
    const float* ln2_s  = (const float*)d_in[6];
    const float* ln2_b  = (const float*)d_in[7];
    const float* w1     = (const float*)d_in[8];
    const float* b1     = (const float*)d_in[9];
    const float* w2     = (const float*)d_in[10];
    const float* b2     = (const float*)d_in[11];

    float* x = (float*)d_out;

    __half *h, *qkv, *o, *mlp, *qkvT, *projT, *w1T, *w2T;
    cudaGetSymbolAddress((void**)&h,     g_h);
    cudaGetSymbolAddress((void**)&qkv,   g_qkv);
    cudaGetSymbolAddress((void**)&o,     g_o);
    cudaGetSymbolAddress((void**)&mlp,   g_mlp);
    cudaGetSymbolAddress((void**)&qkvT,  g_qkvwT);
    cudaGetSymbolAddress((void**)&projT, g_projwT);
    cudaGetSymbolAddress((void**)&w1T,   g_w1T);
    cudaGetSymbolAddress((void**)&w2T,   g_w2T);

    cudaFuncSetAttribute((const void*)mma_gemm<128,0>, cudaFuncAttributeMaxDynamicSharedMemorySize, SMEM128);
    cudaFuncSetAttribute((const void*)mma_gemm<128,1>, cudaFuncAttributeMaxDynamicSharedMemorySize, SMEM128);
    cudaFuncSetAttribute((const void*)mma_gemm<64,2>,  cudaFuncAttributeMaxDynamicSharedMemorySize, SMEM64);

    prep_weights<<<NDEPTH * 3072, dim3(32, 8)>>>(qkv_w, proj_w, w1, w2);

    for (int d = 0; d < NDEPTH; d++) {
        const float* xr = (d == 0) ? x_in : x;

        ln_kernel<<<ROWS, 256>>>(xr, ln1_s + d * Dsz, ln1_b + d * Dsz, h);

        // qkv = h @ qkv_w   (4096 x 1536 x 512)
        mma_gemm<128,0><<<dim3((3 * Dsz) / 128, ROWS / 128), 256, SMEM128>>>(
            h, qkvT + (size_t)d * 3 * Dsz * Dsz, nullptr, nullptr, qkv, 3 * Dsz, Dsz);

        // sparse dilated attention
        dim3 agrid(Tsz / QT, Bsz * Hn);
        if (d == 0)      attn_kernel<1><<<agrid, 256>>>(qkv, o);
        else if (d == 1) attn_kernel<2><<<agrid, 256>>>(qkv, o);
        else             attn_kernel<4><<<agrid, 256>>>(qkv, o);

        // x = xr + o @ proj_w + proj_b   (4096 x 512 x 512)
        mma_gemm<64,2><<<dim3(Dsz / 64, ROWS / 128), 256, SMEM64>>>(
            o, projT + (size_t)d * Dsz * Dsz, proj_b + d * Dsz, xr, x, Dsz, Dsz);

        ln_kernel<<<ROWS, 256>>>(x, ln2_s + d * Dsz, ln2_b + d * Dsz, h);

        // mlp = gelu(h @ w1 + b1)   (4096 x 2048 x 512)
        mma_gemm<128,1><<<dim3((4 * Dsz) / 128, ROWS / 128), 256, SMEM128>>>(
            h, w1T + (size_t)d * Dsz * 4 * Dsz, b1 + (size_t)d * 4 * Dsz, nullptr,
            mlp, 4 * Dsz, Dsz);

        // x = x + mlp @ w2 + b2   (4096 x 512 x 2048)
        mma_gemm<64,2><<<dim3(Dsz / 64, ROWS / 128), 256, SMEM64>>>(
            mlp, w2T + (size_t)d * Dsz * 4 * Dsz, b2 + d * Dsz, x, x, Dsz, 4 * Dsz);
    }
}

// round 8
// speedup vs baseline: 5.5829x; 1.0023x over previous
#include <cuda_runtime.h>
#include <cuda_fp16.h>
#include <math.h>
#include <stdint.h>

#define Bsz   2
#define Tsz   2048
#define Dsz   512
#define Hn    8
#define HDm   64
#define Kw    16
#define NDEPTH 3
#define ROWS  (Bsz*Tsz)   // 4096

// ---------------- scratch (static device globals; no allocation) ----------------
__device__ __half g_h[ROWS * Dsz];
__device__ __half g_qkv[ROWS * 3 * Dsz];
__device__ __half g_o[ROWS * Dsz];
__device__ __half g_mlp[ROWS * 4 * Dsz];
// transposed fp16 weights ([N,K], K contiguous)
__device__ __half g_qkvwT[NDEPTH * 3 * Dsz * Dsz];
__device__ __half g_projwT[NDEPTH * Dsz * Dsz];
__device__ __half g_w1T[NDEPTH * 4 * Dsz * Dsz];
__device__ __half g_w2T[NDEPTH * Dsz * 4 * Dsz];

// ---------------- helpers ----------------------------------------------------------
__device__ __forceinline__ uint32_t smem_u32(const void* p) {
    uint32_t a;
    asm("{ .reg .u64 t; cvta.to.shared.u64 t, %1; cvt.u32.u64 %0, t; }" : "=r"(a) : "l"(p));
    return a;
}
__device__ __forceinline__ void cp16(uint32_t s, const void* g) {
    asm volatile("cp.async.cg.shared.global [%0], [%1], 16;" :: "r"(s), "l"(g));
}
__device__ __forceinline__ void ldsm4(uint32_t* r, uint32_t addr) {
    asm volatile("ldmatrix.sync.aligned.m8n8.x4.shared.b16 {%0,%1,%2,%3}, [%4];"
                 : "=r"(r[0]), "=r"(r[1]), "=r"(r[2]), "=r"(r[3]) : "r"(addr));
}
__device__ __forceinline__ void mma_f16(float* c, const uint32_t* a, const uint32_t* b) {
    asm volatile(
        "mma.sync.aligned.m16n8k16.row.col.f32.f16.f16.f32 "
        "{%0,%1,%2,%3}, {%4,%5,%6,%7}, {%8,%9}, {%0,%1,%2,%3};"
        : "+f"(c[0]), "+f"(c[1]), "+f"(c[2]), "+f"(c[3])
        : "r"(a[0]), "r"(a[1]), "r"(a[2]), "r"(a[3]), "r"(b[0]), "r"(b[1]));
}

// ---------------- fused weight prep: all 12 matrices, fp32 [K,N] -> fp16 [N,K] -----
__global__ void prep_weights(const float* __restrict__ qkv_w, const float* __restrict__ proj_w,
                             const float* __restrict__ w1, const float* __restrict__ w2) {
    __shared__ float tile[32][33];
    int id = blockIdx.x;
    int d  = id / 3072;
    int r  = id % 3072;
    const float* in; __half* out; int R, C, t0;
    if (r < 768)       { in = qkv_w  + (size_t)d * Dsz * 3 * Dsz; out = g_qkvwT  + (size_t)d * 3 * Dsz * Dsz; R = Dsz;     C = 3 * Dsz; t0 = r; }
    else if (r < 1024) { in = proj_w + (size_t)d * Dsz * Dsz;     out = g_projwT + (size_t)d * Dsz * Dsz;     R = Dsz;     C = Dsz;     t0 = r - 768; }
    else if (r < 2048) { in = w1     + (size_t)d * Dsz * 4 * Dsz; out = g_w1T    + (size_t)d * 4 * Dsz * Dsz; R = Dsz;     C = 4 * Dsz; t0 = r - 1024; }
    else               { in = w2     + (size_t)d * 4 * Dsz * Dsz; out = g_w2T    + (size_t)d * Dsz * 4 * Dsz; R = 4 * Dsz; C = Dsz;     t0 = r - 2048; }
    int tpc = C / 32;
    int r0 = (t0 / tpc) * 32, c0 = (t0 % tpc) * 32;
    int tx = threadIdx.x, ty = threadIdx.y;   // (32, 8)
    #pragma unroll
    for (int i = 0; i < 32; i += 8)
        tile[ty + i][tx] = in[(size_t)(r0 + ty + i) * C + c0 + tx];
    __syncthreads();
    #pragma unroll
    for (int i = 0; i < 32; i += 8)
        out[(size_t)(c0 + ty + i) * R + r0 + tx] = __float2half(tile[tx][ty + i]);
}

// ---------------- LayerNorm (fp32 in, fp16 out), shuffle reduction ------------------
__global__ void ln_kernel(const float* __restrict__ x, const float* __restrict__ s,
                          const float* __restrict__ b, __half* __restrict__ out) {
    int row = blockIdx.x;
    int t = threadIdx.x;
    int w = t >> 5, lane = t & 31;
    const float* xr = x + (size_t)row * Dsz;
    float v0 = xr[t], v1 = xr[t + 256];

    float a = v0 + v1, q = v0 * v0 + v1 * v1;
    #pragma unroll
    for (int m = 16; m; m >>= 1) {
        a += __shfl_xor_sync(0xffffffffu, a, m);
        q += __shfl_xor_sync(0xffffffffu, q, m);
    }
    __shared__ float pa[8], pq[8];
    if (lane == 0) { pa[w] = a; pq[w] = q; }
    __syncthreads();
    float ta = 0.f, tq = 0.f;
    #pragma unroll
    for (int i = 0; i < 8; i++) { ta += pa[i]; tq += pq[i]; }
    float mean = ta * (1.0f / Dsz);
    float var  = tq * (1.0f / Dsz) - mean * mean;
    float inv  = rsqrtf(var + 1e-5f);
    __half* orow = out + (size_t)row * Dsz;
    orow[t]       = __float2half((v0 - mean) * inv * s[t]       + b[t]);
    orow[t + 256] = __float2half((v1 - mean) * inv * s[t + 256] + b[t + 256]);
}

// ---------------- Dilated sparse attention: QT=16 queries/block, 128 threads --------
#define QT 16
template <int DIL>
__global__ void __launch_bounds__(128)
attn_kernel(const __half* __restrict__ qkv, __half* __restrict__ o) {
    constexpr int NR = QT + (Kw - 1) * DIL;   // rows staged (max 76 @ DIL=4)
    __shared__ __half sk[NR * HDm];
    __shared__ __half sv[NR * HDm];

    const int tid = threadIdx.x;
    const int b   = blockIdx.y >> 3;
    const int h   = blockIdx.y & 7;
    const int q0  = blockIdx.x * QT;

    const int jlo   = max(0, q0 - (Kw - 1) * DIL);
    const int nrows = q0 + QT - jlo;

    // stage K/V rows [jlo, q0+QT) into smem (uint4 = 8 halves per chunk)
    const __half* kvbase = qkv + ((size_t)(b * Tsz + jlo)) * (3 * Dsz) + h * HDm;
    for (int idx = tid; idx < nrows * 8; idx += 128) {
        int row = idx >> 3, seg = idx & 7;
        const __half* src = kvbase + (size_t)row * (3 * Dsz) + seg * 8;
        *(uint4*)&sk[row * HDm + seg * 8] = *(const uint4*)(src + Dsz);
        *(uint4*)&sv[row * HDm + seg * 8] = *(const uint4*)(src + 2 * Dsz);
    }
    __syncthreads();

    const int l8 = tid & 7;            // owns dims l8*8 .. l8*8+7
    const int q  = q0 + (tid >> 3);    // 16 queries x 8 lanes

    uint4 qv = *(const uint4*)(qkv + ((size_t)(b * Tsz + q)) * (3 * Dsz) + h * HDm + l8 * 8);
    float2 qf[4];
    {
        const __half2* qh = (const __half2*)&qv;
        #pragma unroll
        for (int i = 0; i < 4; i++) qf[i] = __half22float2(qh[i]);
    }

    int nv = q / DIL + 1;
    if (nv > Kw) nv = Kw;

    float sc[Kw];
    #pragma unroll
    for (int s = 0; s < Kw; s++) {
        float e = -1e30f;
        if (s < nv) {
            int r = q - s * DIL - jlo;
            uint4 kv4 = *(const uint4*)&sk[r * HDm + l8 * 8];
            const __half2* kh = (const __half2*)&kv4;
            float p = 0.f;
            #pragma unroll
            for (int i = 0; i < 4; i++) {
                float2 kf = __half22float2(kh[i]);
                p += qf[i].x * kf.x + qf[i].y * kf.y;
            }
            p += __shfl_xor_sync(0xffffffffu, p, 4);
            p += __shfl_xor_sync(0xffffffffu, p, 2);
            p += __shfl_xor_sync(0xffffffffu, p, 1);
            e = p * 0.125f;
        }
        sc[s] = e;
    }
    float mx = sc[0];
    #pragma unroll
    for (int s = 1; s < Kw; s++) mx = fmaxf(mx, sc[s]);

    float denom = 0.f;
    float oa[8] = {0.f, 0.f, 0.f, 0.f, 0.f, 0.f, 0.f, 0.f};
    #pragma unroll
    for (int s = 0; s < Kw; s++) {
        if (s < nv) {
            float wgt = expf(sc[s] - mx);
            denom += wgt;
            int r = q - s * DIL - jlo;
            uint4 vv4 = *(const uint4*)&sv[r * HDm + l8 * 8];
            const __half2* vh = (const __half2*)&vv4;
            #pragma unroll
            for (int i = 0; i < 4; i++) {
                float2 vf = __half22float2(vh[i]);
                oa[2 * i]     += wgt * vf.x;
                oa[2 * i + 1] += wgt * vf.y;
            }
        }
    }
    float rcp = 1.0f / denom;
    __half2 oh[4];
    #pragma unroll
    for (int i = 0; i < 4; i++)
        oh[i] = __floats2half2_rn(oa[2 * i] * rcp, oa[2 * i + 1] * rcp);
    *(uint4*)(o + ((size_t)(b * Tsz + q)) * Dsz + h * HDm + l8 * 8) = *(uint4*)oh;
}

// ---------------- fp16 mma.sync GEMM, S-stage cp.async pipeline ----------------------
// C[M,N] = A[M,K] @ Bt[N,K]^T.  128 x BN_ x BK tile, 256 threads (8 warps: 4M x 2N).
// Rows padded to BK+8 halves (conflict-free ldmatrix). One __syncthreads per chunk.
// EPI: 0 = store half, 1 = +bias + exact GELU -> half, 2 = +bias + residual -> float
template <int BN_, int EPI, int BK, int S>
__global__ void __launch_bounds__(256)
mma_gemm(const __half* __restrict__ A, const __half* __restrict__ Bt,
         const float* __restrict__ bias, const float* __restrict__ res,
         void* __restrict__ Cv, int N, int K) {
    constexpr int BM = 128;
    constexpr int RST = BK + 8;                  // padded row stride (halves)
    constexpr int ABYTES = BM * RST * 2;
    constexpr int BBYTES = BN_ * RST * 2;
    constexpr int WN = BN_ / 2;
    constexpr int NT = WN / 8;
    constexpr int NPAIR = NT / 2;
    constexpr int AITER = (BM * BK / 8) / 256;
    constexpr int BITER = (BN_ * BK / 8) / 256;
    constexpr int KSTEPS = BK / 16;

    extern __shared__ char dsm[];
    const uint32_t sbase = smem_u32(dsm);
    const uint32_t bbase = sbase + S * ABYTES;

    const int tid  = threadIdx.x;
    const int w    = tid >> 5, lane = tid & 31;
    const int wm   = w & 3,   wn   = w >> 2;
    const int g    = lane >> 2, t4 = lane & 3;
    const int quad = lane >> 3, qr = lane & 7;
    const int bx   = blockIdx.x * BN_, by = blockIdx.y * BM;

    const __half* Ag[AITER]; uint32_t Asm[AITER];
    #pragma unroll
    for (int i = 0; i < AITER; i++) {
        int e = tid + i * 256, row = e / (BK / 8), seg = e % (BK / 8);
        Ag[i]  = A + (size_t)(by + row) * K + seg * 8;
        Asm[i] = sbase + (row * RST + seg * 8) * 2;
    }
    const __half* Bg[BITER]; uint32_t Bsm[BITER];
    #pragma unroll
    for (int i = 0; i < BITER; i++) {
        int e = tid + i * 256, row = e / (BK / 8), seg = e % (BK / 8);
        Bg[i]  = Bt + (size_t)(bx + row) * K + seg * 8;
        Bsm[i] = bbase + (row * RST + seg * 8) * 2;
    }

    uint32_t aAddr[2], bAddr[NPAIR];
    #pragma unroll
    for (int mt = 0; mt < 2; mt++) {
        int row = wm * 32 + mt * 16 + (quad & 1) * 8 + qr;
        int col = (quad >> 1) * 8;
        aAddr[mt] = sbase + (row * RST + col) * 2;
    }
    #pragma unroll
    for (int p = 0; p < NPAIR; p++) {
        int row = wn * WN + p * 16 + (quad & 1) * 8 + qr;
        int col = (quad >> 1) * 8;
        bAddr[p] = bbase + (row * RST + col) * 2;
    }

    float acc[2][NT][4];
    #pragma unroll
    for (int i = 0; i < 2; i++)
        #pragma unroll
        for (int j = 0; j < NT; j++)
            #pragma unroll
            for (int q = 0; q < 4; q++) acc[i][j][q] = 0.f;

    const int nch = K / BK;

    // prologue: stages 0..S-2 <- chunks 0..S-2
    #pragma unroll
    for (int s = 0; s < S - 1; s++) {
        const int ko = s * BK;
        #pragma unroll
        for (int i = 0; i < AITER; i++) cp16(Asm[i] + s * ABYTES, Ag[i] + ko);
        #pragma unroll
        for (int i = 0; i < BITER; i++) cp16(Bsm[i] + s * BBYTES, Bg[i] + ko);
        asm volatile("cp.async.commit_group;");
    }

    int cst = 0;            // stage holding chunk c
    int lst = S - 1;        // stage for chunk c+S-1

    for (int c = 0; c < nch; ++c) {
        asm volatile("cp.async.wait_group %0;" :: "n"(S - 2));
        __syncthreads();

        const int ls = c + S - 1;
        if (ls < nch) {
            const int ko = ls * BK;
            #pragma unroll
            for (int i = 0; i < AITER; i++) cp16(Asm[i] + lst * ABYTES, Ag[i] + ko);
            #pragma unroll
            for (int i = 0; i < BITER; i++) cp16(Bsm[i] + lst * BBYTES, Bg[i] + ko);
        }
        asm volatile("cp.async.commit_group;");

        const uint32_t aOff = cst * ABYTES;
        const uint32_t bOff = cst * BBYTES;
        #pragma unroll
        for (int ks = 0; ks < KSTEPS; ks++) {
            const uint32_t kb = ks * 32;   // 16 halves per k-step
            uint32_t af[2][4];
            #pragma unroll
            for (int mt = 0; mt < 2; mt++) ldsm4(af[mt], aAddr[mt] + aOff + kb);
            uint32_t bf[NPAIR][4];
            #pragma unroll
            for (int p = 0; p < NPAIR; p++) ldsm4(bf[p], bAddr[p] + bOff + kb);
            #pragma unroll
            for (int mt = 0; mt < 2; mt++)
                #pragma unroll
                for (int p = 0; p < NPAIR; p++) {
                    uint32_t b0[2] = { bf[p][0], bf[p][2] };
                    uint32_t b1[2] = { bf[p][1], bf[p][3] };
                    mma_f16(acc[mt][2 * p],     af[mt], b0);
                    mma_f16(acc[mt][2 * p + 1], af[mt], b1);
                }
        }
        cst = (cst == S - 1) ? 0 : cst + 1;
        lst = (lst == S - 1) ? 0 : lst + 1;
    }

    // epilogue
    #pragma unroll
    for (int mt = 0; mt < 2; mt++) {
        const int r0 = by + wm * 32 + mt * 16 + g;
        #pragma unroll
        for (int nt = 0; nt < NT; nt++) {
            const int col = bx + wn * WN + nt * 8 + 2 * t4;
            float v0 = acc[mt][nt][0], v1 = acc[mt][nt][1];
            float v2 = acc[mt][nt][2], v3 = acc[mt][nt][3];
            if (EPI != 0) {
                float2 bb = *(const float2*)&bias[col];
                v0 += bb.x; v1 += bb.y; v2 += bb.x; v3 += bb.y;
            }
            if (EPI == 1) {
                v0 = 0.5f * v0 * (1.0f + erff(v0 * 0.70710678118654752f));
                v1 = 0.5f * v1 * (1.0f + erff(v1 * 0.70710678118654752f));
                v2 = 0.5f * v2 * (1.0f + erff(v2 * 0.70710678118654752f));
                v3 = 0.5f * v3 * (1.0f + erff(v3 * 0.70710678118654752f));
            }
            if (EPI == 2) {
                float* C = (float*)Cv;
                float2 ra = *(const float2*)&res[(size_t)r0 * N + col];
                float2 rb = *(const float2*)&res[(size_t)(r0 + 8) * N + col];
                float2 o01 = { v0 + ra.x, v1 + ra.y };
                float2 o23 = { v2 + rb.x, v3 + rb.y };
                *(float2*)&C[(size_t)r0 * N + col]       = o01;
                *(float2*)&C[(size_t)(r0 + 8) * N + col] = o23;
            } else {
                __half* C = (__half*)Cv;
                *(__half2*)&C[(size_t)r0 * N + col]       = __floats2half2_rn(v0, v1);
                *(__half2*)&C[(size_t)(r0 + 8) * N + col] = __floats2half2_rn(v2, v3);
            }
        }
    }
}

// ---------------- launcher -----------------------------------------------------------
// BN=128: BK=64, S=3 -> 3*(18432+18432) = 110592 bytes (2 CTAs/SM)
// BN=64 : BK=32, S=4 -> 4*(10240+5120)  =  61440 bytes (3 CTAs/SM)
#define SMEM128 110592
#define SMEM64  61440

extern "C" void kernel_launch(void* const* d_in, const int* in_sizes, int n_in,
                              void* d_out, int out_size) {
    const float* x_in   = (const float*)d_in[0];
    const float* ln1_s  = (const float*)d_in[1];
    const float* ln1_b  = (const float*)d_in[2];
    const float* qkv_w  = (const float*)d_in[3];
    const float* proj_w = (const float*)d_in[4];
    const float* proj_b = (const float*)d_in[5];
    const float* ln2_s  = (const float*)d_in[6];
    const float* ln2_b  = (const float*)d_in[7];
    const float* w1     = (const float*)d_in[8];
    const float* b1     = (const float*)d_in[9];
    const float* w2     = (const float*)d_in[10];
    const float* b2     = (const float*)d_in[11];

    float* x = (float*)d_out;

    __half *h, *qkv, *o, *mlp, *qkvT, *projT, *w1T, *w2T;
    cudaGetSymbolAddress((void**)&h,     g_h);
    cudaGetSymbolAddress((void**)&qkv,   g_qkv);
    cudaGetSymbolAddress((void**)&o,     g_o);
    cudaGetSymbolAddress((void**)&mlp,   g_mlp);
    cudaGetSymbolAddress((void**)&qkvT,  g_qkvwT);
    cudaGetSymbolAddress((void**)&projT, g_projwT);
    cudaGetSymbolAddress((void**)&w1T,   g_w1T);
    cudaGetSymbolAddress((void**)&w2T,   g_w2T);

    cudaFuncSetAttribute((const void*)mma_gemm<128,0,64,3>, cudaFuncAttributeMaxDynamicSharedMemorySize, SMEM128);
    cudaFuncSetAttribute((const void*)mma_gemm<128,1,64,3>, cudaFuncAttributeMaxDynamicSharedMemorySize, SMEM128);
    cudaFuncSetAttribute((const void*)mma_gemm<64,2,32,4>,  cudaFuncAttributeMaxDynamicSharedMemorySize, SMEM64);

    prep_weights<<<NDEPTH * 3072, dim3(32, 8)>>>(qkv_w, proj_w, w1, w2);

    for (int d = 0; d < NDEPTH; d++) {
        const float* xr = (d == 0) ? x_in : x;

        ln_kernel<<<ROWS, 256>>>(xr, ln1_s + d * Dsz, ln1_b + d * Dsz, h);

        // qkv = h @ qkv_w   (4096 x 1536 x 512)
        mma_gemm<128,0,64,3><<<dim3((3 * Dsz) / 128, ROWS / 128), 256, SMEM128>>>(
            h, qkvT + (size_t)d * 3 * Dsz * Dsz, nullptr, nullptr, qkv, 3 * Dsz, Dsz);

        // sparse dilated attention
        dim3 agrid(Tsz / QT, Bsz * Hn);
        if (d == 0)      attn_kernel<1><<<agrid, 128>>>(qkv, o);
        else if (d == 1) attn_kernel<2><<<agrid, 128>>>(qkv, o);
        else             attn_kernel<4><<<agrid, 128>>>(qkv, o);

        // x = xr + o @ proj_w + proj_b   (4096 x 512 x 512)
        mma_gemm<64,2,32,4><<<dim3(Dsz / 64, ROWS / 128), 256, SMEM64>>>(
            o, projT + (size_t)d * Dsz * Dsz, proj_b + d * Dsz, xr, x, Dsz, Dsz);

        ln_kernel<<<ROWS, 256>>>(x, ln2_s + d * Dsz, ln2_b + d * Dsz, h);

        // mlp = gelu(h @ w1 + b1)   (4096 x 2048 x 512)
        mma_gemm<128,1,64,3><<<dim3((4 * Dsz) / 128, ROWS / 128), 256, SMEM128>>>(
            h, w1T + (size_t)d * Dsz * 4 * Dsz, b1 + (size_t)d * 4 * Dsz, nullptr,
            mlp, 4 * Dsz, Dsz);

        // x = x + mlp @ w2 + b2   (4096 x 512 x 2048)
        mma_gemm<64,2,32,4><<<dim3(Dsz / 64, ROWS / 128), 256, SMEM64>>>(
            mlp, w2T + (size_t)d * Dsz * 4 * Dsz, b2 + d * Dsz, x, x, Dsz, 4 * Dsz);
    }
}